// round 1
// baseline (speedup 1.0000x reference)
#include <cuda_runtime.h>
#include <math.h>

// Problem dims (fixed by the reference)
#define BB 32
#define TT 1024
#define DD 512
#define MM (BB * TT)   // 32768 rows for the dense layers

// Scratch (no allocations allowed -> __device__ globals)
__device__ float g_K[BB * TT * DD];     // K, then exp_K in-place
__device__ float g_V[BB * TT * DD];     // V, then exp_K*V in-place
__device__ float g_Q[BB * TT * DD];     // Q, then Yt in-place
__device__ float g_Kmax[TT * DD];       // max over batch of K
__device__ float g_expw[TT * TT];       // exp(w - rowmax(w))

// ---------------------------------------------------------------------------
// NT SGEMM: C[m,n] = sum_k A[m,k] * W[n,k] + bias[n]
// Tiles: 128x128x8, 256 threads, 8x8 per thread.
// M % 128 == 0, N % 128 == 0, K % 8 == 0 (true for all uses here).
// ---------------------------------------------------------------------------
__global__ __launch_bounds__(256, 2)
void linear_nt_kernel(const float* __restrict__ A,
                      const float* __restrict__ W,
                      const float* __restrict__ bias,
                      float* __restrict__ C,
                      int Mdim, int Ndim, int Kdim)
{
    __shared__ float As[8][128];
    __shared__ float Bs[8][128];

    const int tid = threadIdx.x;
    const int m0 = blockIdx.y * 128;
    const int n0 = blockIdx.x * 128;
    const int ty = tid >> 4;        // 0..15 -> 8 rows each
    const int tx = tid & 15;        // 0..15 -> 8 cols each
    const int lrow = tid >> 1;      // 0..127
    const int lcol = (tid & 1) * 4; // 0 or 4

    const float* Ap = A + (size_t)(m0 + lrow) * Kdim + lcol;
    const float* Wp = W + (size_t)(n0 + lrow) * Kdim + lcol;

    float acc[8][8];
#pragma unroll
    for (int i = 0; i < 8; i++)
#pragma unroll
        for (int j = 0; j < 8; j++) acc[i][j] = 0.f;

    for (int k0 = 0; k0 < Kdim; k0 += 8) {
        float4 av = *(const float4*)(Ap + k0);
        float4 wv = *(const float4*)(Wp + k0);
        As[lcol + 0][lrow] = av.x;
        As[lcol + 1][lrow] = av.y;
        As[lcol + 2][lrow] = av.z;
        As[lcol + 3][lrow] = av.w;
        Bs[lcol + 0][lrow] = wv.x;
        Bs[lcol + 1][lrow] = wv.y;
        Bs[lcol + 2][lrow] = wv.z;
        Bs[lcol + 3][lrow] = wv.w;
        __syncthreads();
#pragma unroll
        for (int k = 0; k < 8; k++) {
            float af[8], bf[8];
            *(float4*)&af[0] = *(const float4*)&As[k][ty * 8];
            *(float4*)&af[4] = *(const float4*)&As[k][ty * 8 + 4];
            *(float4*)&bf[0] = *(const float4*)&Bs[k][tx * 8];
            *(float4*)&bf[4] = *(const float4*)&Bs[k][tx * 8 + 4];
#pragma unroll
            for (int i = 0; i < 8; i++)
#pragma unroll
                for (int j = 0; j < 8; j++)
                    acc[i][j] = fmaf(af[i], bf[j], acc[i][j]);
        }
        __syncthreads();
    }

#pragma unroll
    for (int i = 0; i < 8; i++) {
        const size_t row = (size_t)(m0 + ty * 8 + i);
#pragma unroll
        for (int j = 0; j < 8; j++) {
            const int col = n0 + tx * 8 + j;
            C[row * Ndim + col] = acc[i][j] + bias[col];
        }
    }
}

// ---------------------------------------------------------------------------
// exp_w: per-row max over T then exp(w - max). One block per row.
// ---------------------------------------------------------------------------
__global__ __launch_bounds__(256)
void expw_kernel(const float* __restrict__ w, float* __restrict__ ew)
{
    const int t = blockIdx.x;
    const float* row = w + (size_t)t * TT;

    float m = -INFINITY;
    for (int i = threadIdx.x; i < TT; i += 256)
        m = fmaxf(m, row[i]);
#pragma unroll
    for (int o = 16; o > 0; o >>= 1)
        m = fmaxf(m, __shfl_xor_sync(0xffffffffu, m, o));

    __shared__ float warpmax[8];
    __shared__ float rowmax;
    if ((threadIdx.x & 31) == 0) warpmax[threadIdx.x >> 5] = m;
    __syncthreads();
    if (threadIdx.x == 0) {
        float mm = warpmax[0];
#pragma unroll
        for (int i = 1; i < 8; i++) mm = fmaxf(mm, warpmax[i]);
        rowmax = mm;
    }
    __syncthreads();
    const float rm = rowmax;
    for (int i = threadIdx.x; i < TT; i += 256)
        ew[(size_t)t * TT + i] = expf(row[i] - rm);
}

// ---------------------------------------------------------------------------
// Kmax[t,d] = max over b of K[b,t,d]
// ---------------------------------------------------------------------------
__global__ __launch_bounds__(256)
void kmax_kernel(const float* __restrict__ K, float* __restrict__ Kmax)
{
    const int idx = blockIdx.x * 256 + threadIdx.x;  // < TT*DD
    float m = -INFINITY;
#pragma unroll 4
    for (int b = 0; b < BB; b++)
        m = fmaxf(m, K[(size_t)b * TT * DD + idx]);
    Kmax[idx] = m;
}

// ---------------------------------------------------------------------------
// In-place: K <- exp(K - Kmax), V <- exp(K - Kmax) * V
// ---------------------------------------------------------------------------
__global__ __launch_bounds__(256)
void ekv_kernel(float* __restrict__ K, float* __restrict__ V,
                const float* __restrict__ Kmax)
{
    const size_t idx = (size_t)blockIdx.x * 256 + threadIdx.x;  // < BB*TT*DD
    const float ek = expf(K[idx] - Kmax[idx & (size_t)(TT * DD - 1)]);
    K[idx] = ek;
    V[idx] = ek * V[idx];
}

// ---------------------------------------------------------------------------
// Fused attention GEMM + epilogue:
//   num[t,d] = sum_s expw[t,s] * EKV[b,s,d]
//   den[t,d] = sum_s expw[t,s] * EK [b,s,d]
//   Q[b,t,d] <- sigmoid(Q[b,t,d]) * num/den    (in-place, same element)
// Tiles: 128(t) x 64(d) x 16(s), 256 threads, 8x4 per thread, dual accums.
// ---------------------------------------------------------------------------
__global__ __launch_bounds__(256, 2)
void aft_attn_kernel(const float* __restrict__ expw,
                     const float* __restrict__ EK,
                     const float* __restrict__ EKV,
                     float* __restrict__ Q)
{
    __shared__ float Ws[16][132];   // [s][t], padded
    __shared__ float Eks[16][68];   // [s][d], padded
    __shared__ float Ekvs[16][68];

    const int b  = blockIdx.z;
    const int t0 = blockIdx.y * 128;
    const int d0 = blockIdx.x * 64;
    const int tid = threadIdx.x;
    const int ty = tid >> 4;   // 0..15 -> 8 t-rows each
    const int tx = tid & 15;   // 0..15 -> 4 d-cols each

    const int w_row = tid >> 1;        // 0..127 (t)
    const int w_col = (tid & 1) * 8;   // 0 or 8 (s)
    const int e_row = tid >> 4;        // 0..15  (s)
    const int e_col = (tid & 15) * 4;  // d offset

    const float* ekb  = EK  + (size_t)b * TT * DD;
    const float* ekvb = EKV + (size_t)b * TT * DD;

    float accN[8][4], accD[8][4];
#pragma unroll
    for (int i = 0; i < 8; i++)
#pragma unroll
        for (int j = 0; j < 4; j++) { accN[i][j] = 0.f; accD[i][j] = 0.f; }

    for (int s0 = 0; s0 < TT; s0 += 16) {
        float4 w0 = *(const float4*)(expw + (size_t)(t0 + w_row) * TT + s0 + w_col);
        float4 w1 = *(const float4*)(expw + (size_t)(t0 + w_row) * TT + s0 + w_col + 4);
        Ws[w_col + 0][w_row] = w0.x;
        Ws[w_col + 1][w_row] = w0.y;
        Ws[w_col + 2][w_row] = w0.z;
        Ws[w_col + 3][w_row] = w0.w;
        Ws[w_col + 4][w_row] = w1.x;
        Ws[w_col + 5][w_row] = w1.y;
        Ws[w_col + 6][w_row] = w1.z;
        Ws[w_col + 7][w_row] = w1.w;
        float4 e  = *(const float4*)(ekb  + (size_t)(s0 + e_row) * DD + d0 + e_col);
        float4 ev = *(const float4*)(ekvb + (size_t)(s0 + e_row) * DD + d0 + e_col);
        *(float4*)&Eks[e_row][e_col]  = e;
        *(float4*)&Ekvs[e_row][e_col] = ev;
        __syncthreads();
#pragma unroll
        for (int s = 0; s < 16; s++) {
            float wf[8], ekf[4], ekvf[4];
#pragma unroll
            for (int i = 0; i < 8; i++) wf[i] = Ws[s][ty * 8 + i];
#pragma unroll
            for (int j = 0; j < 4; j++) {
                ekf[j]  = Eks[s][tx * 4 + j];
                ekvf[j] = Ekvs[s][tx * 4 + j];
            }
#pragma unroll
            for (int i = 0; i < 8; i++)
#pragma unroll
                for (int j = 0; j < 4; j++) {
                    accN[i][j] = fmaf(wf[i], ekvf[j], accN[i][j]);
                    accD[i][j] = fmaf(wf[i], ekf[j],  accD[i][j]);
                }
        }
        __syncthreads();
    }

#pragma unroll
    for (int i = 0; i < 8; i++) {
#pragma unroll
        for (int j = 0; j < 4; j++) {
            const size_t idx = (size_t)b * TT * DD
                             + (size_t)(t0 + ty * 8 + i) * DD + d0 + tx * 4 + j;
            const float q = Q[idx];
            const float sig = 1.f / (1.f + expf(-q));
            Q[idx] = sig * accN[i][j] / accD[i][j];
        }
    }
}

// ---------------------------------------------------------------------------
extern "C" void kernel_launch(void* const* d_in, const int* in_sizes, int n_in,
                              void* d_out, int out_size)
{
    const float* x    = (const float*)d_in[0];
    const float* Wk_w = (const float*)d_in[1];
    const float* Wk_b = (const float*)d_in[2];
    const float* Wv_w = (const float*)d_in[3];
    const float* Wv_b = (const float*)d_in[4];
    const float* Wq_w = (const float*)d_in[5];
    const float* Wq_b = (const float*)d_in[6];
    const float* w    = (const float*)d_in[7];
    const float* Wo_w = (const float*)d_in[8];
    const float* Wo_b = (const float*)d_in[9];
    float* out = (float*)d_out;

    float *pK, *pV, *pQ, *pKmax, *pexpw;
    cudaGetSymbolAddress((void**)&pK, g_K);
    cudaGetSymbolAddress((void**)&pV, g_V);
    cudaGetSymbolAddress((void**)&pQ, g_Q);
    cudaGetSymbolAddress((void**)&pKmax, g_Kmax);
    cudaGetSymbolAddress((void**)&pexpw, g_expw);

    const dim3 lin_grid(DD / 128, MM / 128);  // (4, 256)
    linear_nt_kernel<<<lin_grid, 256>>>(x, Wk_w, Wk_b, pK, MM, DD, DD);
    linear_nt_kernel<<<lin_grid, 256>>>(x, Wv_w, Wv_b, pV, MM, DD, DD);
    linear_nt_kernel<<<lin_grid, 256>>>(x, Wq_w, Wq_b, pQ, MM, DD, DD);

    expw_kernel<<<TT, 256>>>(w, pexpw);
    kmax_kernel<<<(TT * DD) / 256, 256>>>(pK, pKmax);
    ekv_kernel<<<(BB * TT * DD) / 256, 256>>>(pK, pV, pKmax);

    const dim3 attn_grid(DD / 64, TT / 128, BB);  // (8, 8, 32)
    aft_attn_kernel<<<attn_grid, 256>>>(pexpw, pK, pV, pQ);

    linear_nt_kernel<<<lin_grid, 256>>>(pQ, Wo_w, Wo_b, out, MM, DD, DD);
}

// round 2
// speedup vs baseline: 1.5013x; 1.5013x over previous
#include <cuda_runtime.h>
#include <mma.h>
#include <math.h>

using namespace nvcuda;

#define BB 32
#define TT 1024
#define DD 512
#define MM (BB * TT)

// Scratch (__device__ globals; no allocations allowed)
__device__ float g_K[BB * TT * DD];
__device__ float g_V[BB * TT * DD];
__device__ float g_Q[BB * TT * DD];
__device__ float g_Kmax[TT * DD];
__device__ float g_expw[TT * TT];
__device__ float g_brep[16 * DD];   // replicated output bias for accumulator init

// ---------------------------------------------------------------------------
// tf32 WMMA NT GEMM: C[m,n] = sum_k A[m,k] * W[n,k]  (+ optional bias via brep)
// Block tile 128x128, K-chunk 16. 8 warps (4x2), warp tile 32x64 (2x4 wmma).
// ---------------------------------------------------------------------------
struct StageL { float As[128][24]; float Ws[128][24]; };
struct EpiL   { float buf[128][72]; };
union SmemL { StageL s; EpiL e; };

__global__ __launch_bounds__(256)
void linear_wmma(const float* __restrict__ A,
                 const float* __restrict__ W,
                 const float* __restrict__ brep,   // [16][DD] replicated bias or null
                 float* __restrict__ C,
                 int Mdim, int Ndim, int Kdim)
{
    __shared__ SmemL u;

    const int tid = threadIdx.x;
    const int wid = tid >> 5;
    const int warpM = wid >> 1;       // 0..3
    const int warpN = wid & 1;        // 0..1
    const int m0 = blockIdx.y * 128;
    const int n0 = blockIdx.x * 128;

    wmma::fragment<wmma::accumulator, 16, 16, 8, float> c[2][4];
#pragma unroll
    for (int i = 0; i < 2; i++)
#pragma unroll
        for (int j = 0; j < 4; j++) {
            if (brep)
                wmma::load_matrix_sync(c[i][j],
                    brep + n0 + warpN * 64 + j * 16, DD, wmma::mem_row_major);
            else
                wmma::fill_fragment(c[i][j], 0.0f);
        }

    for (int k0 = 0; k0 < Kdim; k0 += 16) {
#pragma unroll
        for (int i = 0; i < 2; i++) {
            const int f = tid * 2 + i;       // 0..511
            const int row = f >> 2;          // 0..127
            const int c4 = f & 3;            // 0..3
            float4 av = *(const float4*)(A + (size_t)(m0 + row) * Kdim + k0 + c4 * 4);
            float4 wv = *(const float4*)(W + (size_t)(n0 + row) * Kdim + k0 + c4 * 4);
            u.s.As[row][c4 * 4 + 0] = wmma::__float_to_tf32(av.x);
            u.s.As[row][c4 * 4 + 1] = wmma::__float_to_tf32(av.y);
            u.s.As[row][c4 * 4 + 2] = wmma::__float_to_tf32(av.z);
            u.s.As[row][c4 * 4 + 3] = wmma::__float_to_tf32(av.w);
            u.s.Ws[row][c4 * 4 + 0] = wmma::__float_to_tf32(wv.x);
            u.s.Ws[row][c4 * 4 + 1] = wmma::__float_to_tf32(wv.y);
            u.s.Ws[row][c4 * 4 + 2] = wmma::__float_to_tf32(wv.z);
            u.s.Ws[row][c4 * 4 + 3] = wmma::__float_to_tf32(wv.w);
        }
        __syncthreads();
#pragma unroll
        for (int kk = 0; kk < 16; kk += 8) {
            wmma::fragment<wmma::matrix_a, 16, 16, 8, wmma::precision::tf32, wmma::row_major> a[2];
            wmma::fragment<wmma::matrix_b, 16, 16, 8, wmma::precision::tf32, wmma::col_major> b[4];
#pragma unroll
            for (int i = 0; i < 2; i++)
                wmma::load_matrix_sync(a[i], &u.s.As[warpM * 32 + i * 16][kk], 24);
#pragma unroll
            for (int j = 0; j < 4; j++)
                wmma::load_matrix_sync(b[j], &u.s.Ws[warpN * 64 + j * 16][kk], 24);
#pragma unroll
            for (int i = 0; i < 2; i++)
#pragma unroll
                for (int j = 0; j < 4; j++)
                    wmma::mma_sync(c[i][j], a[i], b[j], c[i][j]);
        }
        __syncthreads();
    }

    // Epilogue: two passes through a 128x64 smem buffer (one per warpN half)
#pragma unroll
    for (int p = 0; p < 2; p++) {
        if (warpN == p) {
#pragma unroll
            for (int i = 0; i < 2; i++)
#pragma unroll
                for (int j = 0; j < 4; j++)
                    wmma::store_matrix_sync(&u.e.buf[warpM * 32 + i * 16][j * 16],
                                            c[i][j], 72, wmma::mem_row_major);
        }
        __syncthreads();
#pragma unroll
        for (int it = 0; it < 8; it++) {
            const int f = tid + it * 256;    // 0..2047 (f4 index over 128x64)
            const int row = f >> 4;
            const int c4 = f & 15;
            float4 v = *(const float4*)&u.e.buf[row][c4 * 4];
            *(float4*)(C + (size_t)(m0 + row) * Ndim + n0 + p * 64 + c4 * 4) = v;
        }
        __syncthreads();
    }
}

// ---------------------------------------------------------------------------
// exp_w: per-row max then exp(w - max). One block per row.
// ---------------------------------------------------------------------------
__global__ __launch_bounds__(256)
void expw_kernel(const float* __restrict__ w, float* __restrict__ ew)
{
    const int t = blockIdx.x;
    const float* row = w + (size_t)t * TT;

    float m = -INFINITY;
    for (int i = threadIdx.x; i < TT; i += 256)
        m = fmaxf(m, row[i]);
#pragma unroll
    for (int o = 16; o > 0; o >>= 1)
        m = fmaxf(m, __shfl_xor_sync(0xffffffffu, m, o));

    __shared__ float warpmax[8];
    __shared__ float rowmax;
    if ((threadIdx.x & 31) == 0) warpmax[threadIdx.x >> 5] = m;
    __syncthreads();
    if (threadIdx.x == 0) {
        float mm = warpmax[0];
#pragma unroll
        for (int i = 1; i < 8; i++) mm = fmaxf(mm, warpmax[i]);
        rowmax = mm;
    }
    __syncthreads();
    const float rm = rowmax;
    for (int i = threadIdx.x; i < TT; i += 256)
        ew[(size_t)t * TT + i] = expf(row[i] - rm);
}

// ---------------------------------------------------------------------------
// Kmax[t,d] = max_b K[b,t,d]   (K here has NO bias; bias cancels in exp)
// ---------------------------------------------------------------------------
__global__ __launch_bounds__(256)
void kmax_kernel(const float* __restrict__ K, float* __restrict__ Kmax)
{
    const int idx = blockIdx.x * 256 + threadIdx.x;
    float m = -INFINITY;
#pragma unroll 4
    for (int b = 0; b < BB; b++)
        m = fmaxf(m, K[(size_t)b * TT * DD + idx]);
    Kmax[idx] = m;
}

// ---------------------------------------------------------------------------
// K <- exp(K - Kmax), V <- exp(K - Kmax) * (V + bv)   (V bias folded here)
// ---------------------------------------------------------------------------
__global__ __launch_bounds__(256)
void ekv_kernel(float* __restrict__ K, float* __restrict__ V,
                const float* __restrict__ Kmax, const float* __restrict__ bv)
{
    const size_t idx = (size_t)blockIdx.x * 256 + threadIdx.x;
    const float ek = expf(K[idx] - Kmax[idx & (size_t)(TT * DD - 1)]);
    K[idx] = ek;
    V[idx] = ek * (V[idx] + bv[idx & (DD - 1)]);
}

// ---------------------------------------------------------------------------
// Fused attention (tf32 WMMA) + epilogue:
//   num = expw @ EKV, den = expw @ EK  (per batch), Q <- sigmoid(Q+bq)*num/den
// Block tile 64(t) x 64(d), K-chunk 16. 4 warps (2x2), warp tile 32x32.
// ---------------------------------------------------------------------------
struct StageA { float ew[64][24]; float ek[16][72]; float ekv[16][72]; };
struct EpiA   { float num[64][72]; float den[64][72]; };
union SmemA { StageA s; EpiA e; };

__global__ __launch_bounds__(128)
void aft_attn_wmma(const float* __restrict__ expw,
                   const float* __restrict__ EK,
                   const float* __restrict__ EKV,
                   float* __restrict__ Q,
                   const float* __restrict__ bq)
{
    __shared__ SmemA u;

    const int tid = threadIdx.x;
    const int wid = tid >> 5;
    const int wm = wid >> 1;          // 0..1
    const int wn = wid & 1;           // 0..1
    const int b  = blockIdx.z;
    const int t0 = blockIdx.y * 64;
    const int d0 = blockIdx.x * 64;

    const float* ekb  = EK  + (size_t)b * TT * DD;
    const float* ekvb = EKV + (size_t)b * TT * DD;

    wmma::fragment<wmma::accumulator, 16, 16, 8, float> cN[2][2], cD[2][2];
#pragma unroll
    for (int i = 0; i < 2; i++)
#pragma unroll
        for (int j = 0; j < 2; j++) {
            wmma::fill_fragment(cN[i][j], 0.0f);
            wmma::fill_fragment(cD[i][j], 0.0f);
        }

    for (int s0 = 0; s0 < TT; s0 += 16) {
#pragma unroll
        for (int i = 0; i < 2; i++) {
            const int f = tid * 2 + i;           // 0..255
            {   // expw tile: 64 x 16
                const int row = f >> 2, c4 = f & 3;
                float4 v = *(const float4*)(expw + (size_t)(t0 + row) * TT + s0 + c4 * 4);
                u.s.ew[row][c4 * 4 + 0] = wmma::__float_to_tf32(v.x);
                u.s.ew[row][c4 * 4 + 1] = wmma::__float_to_tf32(v.y);
                u.s.ew[row][c4 * 4 + 2] = wmma::__float_to_tf32(v.z);
                u.s.ew[row][c4 * 4 + 3] = wmma::__float_to_tf32(v.w);
            }
            {   // EK / EKV tiles: 16 x 64
                const int row = f >> 4, c4 = f & 15;
                float4 e  = *(const float4*)(ekb  + (size_t)(s0 + row) * DD + d0 + c4 * 4);
                float4 ev = *(const float4*)(ekvb + (size_t)(s0 + row) * DD + d0 + c4 * 4);
                u.s.ek[row][c4 * 4 + 0]  = wmma::__float_to_tf32(e.x);
                u.s.ek[row][c4 * 4 + 1]  = wmma::__float_to_tf32(e.y);
                u.s.ek[row][c4 * 4 + 2]  = wmma::__float_to_tf32(e.z);
                u.s.ek[row][c4 * 4 + 3]  = wmma::__float_to_tf32(e.w);
                u.s.ekv[row][c4 * 4 + 0] = wmma::__float_to_tf32(ev.x);
                u.s.ekv[row][c4 * 4 + 1] = wmma::__float_to_tf32(ev.y);
                u.s.ekv[row][c4 * 4 + 2] = wmma::__float_to_tf32(ev.z);
                u.s.ekv[row][c4 * 4 + 3] = wmma::__float_to_tf32(ev.w);
            }
        }
        __syncthreads();
#pragma unroll
        for (int kk = 0; kk < 16; kk += 8) {
            wmma::fragment<wmma::matrix_a, 16, 16, 8, wmma::precision::tf32, wmma::row_major> a[2];
            wmma::fragment<wmma::matrix_b, 16, 16, 8, wmma::precision::tf32, wmma::row_major> bK[2], bV[2];
#pragma unroll
            for (int i = 0; i < 2; i++)
                wmma::load_matrix_sync(a[i], &u.s.ew[wm * 32 + i * 16][kk], 24);
#pragma unroll
            for (int j = 0; j < 2; j++) {
                wmma::load_matrix_sync(bK[j], &u.s.ek[kk][wn * 32 + j * 16], 72);
                wmma::load_matrix_sync(bV[j], &u.s.ekv[kk][wn * 32 + j * 16], 72);
            }
#pragma unroll
            for (int i = 0; i < 2; i++)
#pragma unroll
                for (int j = 0; j < 2; j++) {
                    wmma::mma_sync(cN[i][j], a[i], bV[j], cN[i][j]);
                    wmma::mma_sync(cD[i][j], a[i], bK[j], cD[i][j]);
                }
        }
        __syncthreads();
    }

    // Epilogue: stage num/den in smem, apply sigmoid(Q+bq)*num/den in-place on Q
#pragma unroll
    for (int i = 0; i < 2; i++)
#pragma unroll
        for (int j = 0; j < 2; j++) {
            wmma::store_matrix_sync(&u.e.num[wm * 32 + i * 16][wn * 32 + j * 16],
                                    cN[i][j], 72, wmma::mem_row_major);
            wmma::store_matrix_sync(&u.e.den[wm * 32 + i * 16][wn * 32 + j * 16],
                                    cD[i][j], 72, wmma::mem_row_major);
        }
    __syncthreads();

#pragma unroll
    for (int it = 0; it < 8; it++) {
        const int f = tid + it * 128;        // 0..1023 f4 over 64x64
        const int row = f >> 4;
        const int c4 = f & 15;
        const size_t qidx = (size_t)b * TT * DD + (size_t)(t0 + row) * DD + d0 + c4 * 4;
        float4 q = *(const float4*)(Q + qidx);
        float4 nm = *(const float4*)&u.e.num[row][c4 * 4];
        float4 dn = *(const float4*)&u.e.den[row][c4 * 4];
        const int dcol = d0 + c4 * 4;
        float4 r;
        r.x = (1.f / (1.f + expf(-(q.x + bq[dcol + 0])))) * nm.x / dn.x;
        r.y = (1.f / (1.f + expf(-(q.y + bq[dcol + 1])))) * nm.y / dn.y;
        r.z = (1.f / (1.f + expf(-(q.z + bq[dcol + 2])))) * nm.z / dn.z;
        r.w = (1.f / (1.f + expf(-(q.w + bq[dcol + 3])))) * nm.w / dn.w;
        *(float4*)(Q + qidx) = r;
    }
}

// ---------------------------------------------------------------------------
// Fill replicated bias tile brep[16][DD] = bo
// ---------------------------------------------------------------------------
__global__ void brep_fill(const float* __restrict__ bo, float* __restrict__ brep)
{
    const int idx = blockIdx.x * 256 + threadIdx.x;   // < 16*DD
    brep[idx] = bo[idx & (DD - 1)];
}

// ---------------------------------------------------------------------------
extern "C" void kernel_launch(void* const* d_in, const int* in_sizes, int n_in,
                              void* d_out, int out_size)
{
    const float* x    = (const float*)d_in[0];
    const float* Wk_w = (const float*)d_in[1];
    // Wk_b unused: bias cancels inside exp(K - max_b K)
    const float* Wv_w = (const float*)d_in[3];
    const float* Wv_b = (const float*)d_in[4];
    const float* Wq_w = (const float*)d_in[5];
    const float* Wq_b = (const float*)d_in[6];
    const float* w    = (const float*)d_in[7];
    const float* Wo_w = (const float*)d_in[8];
    const float* Wo_b = (const float*)d_in[9];
    float* out = (float*)d_out;

    float *pK, *pV, *pQ, *pKmax, *pexpw, *pbrep;
    cudaGetSymbolAddress((void**)&pK, g_K);
    cudaGetSymbolAddress((void**)&pV, g_V);
    cudaGetSymbolAddress((void**)&pQ, g_Q);
    cudaGetSymbolAddress((void**)&pKmax, g_Kmax);
    cudaGetSymbolAddress((void**)&pexpw, g_expw);
    cudaGetSymbolAddress((void**)&pbrep, g_brep);

    const dim3 lin_grid(DD / 128, MM / 128);   // (4, 256)
    linear_wmma<<<lin_grid, 256>>>(x, Wk_w, nullptr, pK, MM, DD, DD);
    linear_wmma<<<lin_grid, 256>>>(x, Wv_w, nullptr, pV, MM, DD, DD);
    linear_wmma<<<lin_grid, 256>>>(x, Wq_w, nullptr, pQ, MM, DD, DD);

    expw_kernel<<<TT, 256>>>(w, pexpw);
    kmax_kernel<<<(TT * DD) / 256, 256>>>(pK, pKmax);
    ekv_kernel<<<(BB * TT * DD) / 256, 256>>>(pK, pV, pKmax, Wv_b);

    const dim3 attn_grid(DD / 64, TT / 64, BB);  // (8, 16, 32)
    aft_attn_wmma<<<attn_grid, 128>>>(pexpw, pK, pV, pQ, Wq_b);

    brep_fill<<<(16 * DD) / 256, 256>>>(Wo_b, pbrep);
    linear_wmma<<<lin_grid, 256>>>(pQ, Wo_w, pbrep, out, MM, DD, DD);
}

// round 4
// speedup vs baseline: 1.6317x; 1.0869x over previous
#include <cuda_runtime.h>
#include <math.h>
#include <mma.h>
#include <stdint.h>

using namespace nvcuda;

#define BB 32
#define TT 1024
#define DD 512
#define MM (BB * TT)

// Scratch (__device__ globals; no allocations allowed)
__device__ float g_K[MM * DD];
__device__ float g_V[MM * DD];
__device__ float g_Q[MM * DD];
__device__ float g_Kmax[TT * DD];
__device__ float g_expw[TT * TT];
__device__ float g_brep[16 * DD];

__device__ __forceinline__ uint32_t smem_u32(const void* p) {
    uint32_t a;
    asm("{ .reg .u64 t; cvta.to.shared.u64 t, %1; cvt.u32.u64 %0, t; }"
        : "=r"(a) : "l"(p));
    return a;
}

#define CP16(dst_f, src_f) \
    asm volatile("cp.async.cg.shared.global [%0], [%1], 16;" \
        :: "r"(smem_u32(dst_f)), "l"((const void*)(src_f)) : "memory")
#define CP_COMMIT() asm volatile("cp.async.commit_group;" ::: "memory")
#define CP_WAIT1()  asm volatile("cp.async.wait_group 1;" ::: "memory")

// ===========================================================================
// Linear NT GEMM (tf32 WMMA + cp.async 3-stage pipeline)
//   C[m,n] = sum_k A[m,k] * W[n,k]  (+ bias via replicated-bias acc init)
// Block 128x128, K-chunk 32, 256 threads, 8 warps (2Mx4N), warp tile 64x32.
// ===========================================================================
#define L_STAGE 9216           // floats per stage: As 128*36 + Bs 128*36
#define L_NST 3
#define L_SMEM (L_NST * L_STAGE * 4)

__global__ __launch_bounds__(256)
void lin2(const float* __restrict__ A, const float* __restrict__ W,
          const float* __restrict__ brep, float* __restrict__ C, int has_bias)
{
    extern __shared__ float sm[];
    const int tid = threadIdx.x;
    const int wid = tid >> 5;
    const int wm = wid >> 2;          // 0..1  (64 rows)
    const int wn = wid & 3;           // 0..3  (32 cols)
    const int m0 = blockIdx.y * 128, n0 = blockIdx.x * 128;

    wmma::fragment<wmma::accumulator, 16, 16, 8, float> c[4][2];
#pragma unroll
    for (int i = 0; i < 4; i++)
#pragma unroll
        for (int j = 0; j < 2; j++) {
            if (has_bias)
                wmma::load_matrix_sync(c[i][j], brep + n0 + wn * 32 + j * 16,
                                       DD, wmma::mem_row_major);
            else
                wmma::fill_fragment(c[i][j], 0.0f);
        }

    auto issue = [&](int chunk, int st) {
        float* As = sm + st * L_STAGE;
        float* Bs = As + 4608;
        const int k0 = chunk * 32;
#pragma unroll
        for (int i = 0; i < 4; i++) {
            const int f = tid + i * 256;       // 0..1023
            const int row = f >> 3, c4 = f & 7;
            CP16(As + row * 36 + c4 * 4, A + (size_t)(m0 + row) * DD + k0 + c4 * 4);
            CP16(Bs + row * 36 + c4 * 4, W + (size_t)(n0 + row) * DD + k0 + c4 * 4);
        }
        CP_COMMIT();
    };

    issue(0, 0);
    issue(1, 1);

    const int NC = DD / 32;   // 16
    for (int ch = 0; ch < NC; ch++) {
        CP_WAIT1();
        __syncthreads();
        if (ch + 2 < NC) issue(ch + 2, (ch + 2) % L_NST);

        const float* As = sm + (ch % L_NST) * L_STAGE;
        const float* Bs = As + 4608;
#pragma unroll
        for (int kk = 0; kk < 4; kk++) {
            wmma::fragment<wmma::matrix_a, 16, 16, 8, wmma::precision::tf32, wmma::row_major> a[4];
            wmma::fragment<wmma::matrix_b, 16, 16, 8, wmma::precision::tf32, wmma::col_major> b[2];
#pragma unroll
            for (int i = 0; i < 4; i++)
                wmma::load_matrix_sync(a[i], As + (wm * 64 + i * 16) * 36 + kk * 8, 36);
#pragma unroll
            for (int j = 0; j < 2; j++)
                wmma::load_matrix_sync(b[j], Bs + (wn * 32 + j * 16) * 36 + kk * 8, 36);
#pragma unroll
            for (int i = 0; i < 4; i++)
#pragma unroll
                for (int j = 0; j < 2; j++)
                    wmma::mma_sync(c[i][j], a[i], b[j], c[i][j]);
        }
    }

    // Direct epilogue to gmem
#pragma unroll
    for (int i = 0; i < 4; i++)
#pragma unroll
        for (int j = 0; j < 2; j++)
            wmma::store_matrix_sync(C + (size_t)(m0 + wm * 64 + i * 16) * DD
                                      + n0 + wn * 32 + j * 16,
                                    c[i][j], DD, wmma::mem_row_major);
}

// ===========================================================================
// Attention: num = expw @ EKV, den = expw @ EK (per batch, row-major B),
// epilogue Q <- sigmoid(Q + bq) * num / den.
// Block 128(t) x 64(d), K(s)-chunk 32, 256 threads, 8 warps (4Mx2N),
// warp tile 32x32. 3-stage cp.async pipeline.
// ===========================================================================
#define A_STAGE 8960           // floats: Ws 128*36 + EK 32*68 + EKV 32*68
#define A_NST 3
#define A_SMEM (A_NST * A_STAGE * 4)

__global__ __launch_bounds__(256)
void attn2(const float* __restrict__ expw, const float* __restrict__ EK,
           const float* __restrict__ EKV, float* __restrict__ Q,
           const float* __restrict__ bq)
{
    extern __shared__ float sm[];
    const int tid = threadIdx.x;
    const int wid = tid >> 5;
    const int wm = wid >> 1;          // 0..3 (32 t-rows)
    const int wn = wid & 1;           // 0..1 (32 d-cols)
    const int d0 = blockIdx.x * 64, t0 = blockIdx.y * 128, b = blockIdx.z;

    const float* ekb  = EK  + (size_t)b * TT * DD;
    const float* ekvb = EKV + (size_t)b * TT * DD;

    wmma::fragment<wmma::accumulator, 16, 16, 8, float> cN[2][2], cD[2][2];
#pragma unroll
    for (int i = 0; i < 2; i++)
#pragma unroll
        for (int j = 0; j < 2; j++) {
            wmma::fill_fragment(cN[i][j], 0.0f);
            wmma::fill_fragment(cD[i][j], 0.0f);
        }

    auto issue = [&](int chunk, int st) {
        float* Ws  = sm + st * A_STAGE;
        float* EKs = Ws + 4608;
        float* EVs = EKs + 2176;
        const int s0 = chunk * 32;
#pragma unroll
        for (int i = 0; i < 4; i++) {
            const int f = tid + i * 256;
            const int row = f >> 3, c4 = f & 7;
            CP16(Ws + row * 36 + c4 * 4, expw + (size_t)(t0 + row) * TT + s0 + c4 * 4);
        }
#pragma unroll
        for (int i = 0; i < 2; i++) {
            const int f = tid + i * 256;       // 0..511
            const int row = f >> 4, c4 = f & 15;
            CP16(EKs + row * 68 + c4 * 4, ekb  + (size_t)(s0 + row) * DD + d0 + c4 * 4);
            CP16(EVs + row * 68 + c4 * 4, ekvb + (size_t)(s0 + row) * DD + d0 + c4 * 4);
        }
        CP_COMMIT();
    };

    issue(0, 0);
    issue(1, 1);

    const int NC = TT / 32;   // 32
    for (int ch = 0; ch < NC; ch++) {
        CP_WAIT1();
        __syncthreads();
        if (ch + 2 < NC) issue(ch + 2, (ch + 2) % A_NST);

        const float* Ws  = sm + (ch % A_NST) * A_STAGE;
        const float* EKs = Ws + 4608;
        const float* EVs = EKs + 2176;
#pragma unroll
        for (int kk = 0; kk < 4; kk++) {
            wmma::fragment<wmma::matrix_a, 16, 16, 8, wmma::precision::tf32, wmma::row_major> a[2];
            wmma::fragment<wmma::matrix_b, 16, 16, 8, wmma::precision::tf32, wmma::row_major> bK[2], bV[2];
#pragma unroll
            for (int i = 0; i < 2; i++)
                wmma::load_matrix_sync(a[i], Ws + (wm * 32 + i * 16) * 36 + kk * 8, 36);
#pragma unroll
            for (int j = 0; j < 2; j++) {
                wmma::load_matrix_sync(bK[j], EKs + (kk * 8) * 68 + wn * 32 + j * 16, 68);
                wmma::load_matrix_sync(bV[j], EVs + (kk * 8) * 68 + wn * 32 + j * 16, 68);
            }
#pragma unroll
            for (int i = 0; i < 2; i++)
#pragma unroll
                for (int j = 0; j < 2; j++) {
                    wmma::mma_sync(cN[i][j], a[i], bV[j], cN[i][j]);
                    wmma::mma_sync(cD[i][j], a[i], bK[j], cD[i][j]);
                }
        }
    }

    // Epilogue: stage num/den in (reused) smem, apply sigmoid(Q+bq)*num/den
    __syncthreads();
    float* num = sm;                 // [128][68]
    float* den = sm + 128 * 68;      // [128][68]
#pragma unroll
    for (int i = 0; i < 2; i++)
#pragma unroll
        for (int j = 0; j < 2; j++) {
            wmma::store_matrix_sync(&num[(wm * 32 + i * 16) * 68 + wn * 32 + j * 16],
                                    cN[i][j], 68, wmma::mem_row_major);
            wmma::store_matrix_sync(&den[(wm * 32 + i * 16) * 68 + wn * 32 + j * 16],
                                    cD[i][j], 68, wmma::mem_row_major);
        }
    __syncthreads();

#pragma unroll
    for (int it = 0; it < 8; it++) {
        const int f = tid + it * 256;        // 0..2047 f4 over 128x64
        const int row = f >> 4, c4 = f & 15;
        const size_t qidx = ((size_t)b * TT + t0 + row) * DD + d0 + c4 * 4;
        float4 q = *(const float4*)(Q + qidx);
        float4 b4 = __ldg((const float4*)(bq + d0 + c4 * 4));
        const float* np = &num[row * 68 + c4 * 4];
        const float* dp = &den[row * 68 + c4 * 4];
        float4 o;
        o.x = (1.f / (1.f + expf(-(q.x + b4.x)))) * np[0] / dp[0];
        o.y = (1.f / (1.f + expf(-(q.y + b4.y)))) * np[1] / dp[1];
        o.z = (1.f / (1.f + expf(-(q.z + b4.z)))) * np[2] / dp[2];
        o.w = (1.f / (1.f + expf(-(q.w + b4.w)))) * np[3] / dp[3];
        *(float4*)(Q + qidx) = o;
    }
}

// ===========================================================================
// Elementwise kernels (validated in R1/R2)
// ===========================================================================
__global__ __launch_bounds__(256)
void expw_kernel(const float* __restrict__ w, float* __restrict__ ew)
{
    const int t = blockIdx.x;
    const float* row = w + (size_t)t * TT;
    float m = -INFINITY;
    for (int i = threadIdx.x; i < TT; i += 256) m = fmaxf(m, row[i]);
#pragma unroll
    for (int o = 16; o > 0; o >>= 1) m = fmaxf(m, __shfl_xor_sync(0xffffffffu, m, o));
    __shared__ float warpmax[8];
    __shared__ float rowmax;
    if ((threadIdx.x & 31) == 0) warpmax[threadIdx.x >> 5] = m;
    __syncthreads();
    if (threadIdx.x == 0) {
        float mm = warpmax[0];
#pragma unroll
        for (int i = 1; i < 8; i++) mm = fmaxf(mm, warpmax[i]);
        rowmax = mm;
    }
    __syncthreads();
    const float rm = rowmax;
    for (int i = threadIdx.x; i < TT; i += 256)
        ew[(size_t)t * TT + i] = expf(row[i] - rm);
}

__global__ __launch_bounds__(256)
void kmax_kernel(const float* __restrict__ K, float* __restrict__ Kmax)
{
    const int idx = blockIdx.x * 256 + threadIdx.x;
    float m = -INFINITY;
#pragma unroll 4
    for (int b = 0; b < BB; b++)
        m = fmaxf(m, K[(size_t)b * TT * DD + idx]);
    Kmax[idx] = m;
}

__global__ __launch_bounds__(256)
void ekv_kernel(float* __restrict__ K, float* __restrict__ V,
                const float* __restrict__ Kmax, const float* __restrict__ bv)
{
    const size_t idx = (size_t)blockIdx.x * 256 + threadIdx.x;
    const float ek = expf(K[idx] - Kmax[idx & (size_t)(TT * DD - 1)]);
    K[idx] = ek;
    V[idx] = ek * (V[idx] + bv[idx & (DD - 1)]);
}

__global__ void brep_fill(const float* __restrict__ bo, float* __restrict__ brep)
{
    const int idx = blockIdx.x * 256 + threadIdx.x;
    brep[idx] = bo[idx & (DD - 1)];
}

// ===========================================================================
extern "C" void kernel_launch(void* const* d_in, const int* in_sizes, int n_in,
                              void* d_out, int out_size)
{
    const float* x    = (const float*)d_in[0];
    const float* Wk_w = (const float*)d_in[1];
    // Wk_b unused: K bias cancels inside exp(K - max_b K)
    const float* Wv_w = (const float*)d_in[3];
    const float* Wv_b = (const float*)d_in[4];
    const float* Wq_w = (const float*)d_in[5];
    const float* Wq_b = (const float*)d_in[6];
    const float* w    = (const float*)d_in[7];
    const float* Wo_w = (const float*)d_in[8];
    const float* Wo_b = (const float*)d_in[9];
    float* out = (float*)d_out;

    float *pK, *pV, *pQ, *pKmax, *pexpw, *pbrep;
    cudaGetSymbolAddress((void**)&pK, g_K);
    cudaGetSymbolAddress((void**)&pV, g_V);
    cudaGetSymbolAddress((void**)&pQ, g_Q);
    cudaGetSymbolAddress((void**)&pKmax, g_Kmax);
    cudaGetSymbolAddress((void**)&pexpw, g_expw);
    cudaGetSymbolAddress((void**)&pbrep, g_brep);

    static int attr_done = 0;
    if (!attr_done) {
        cudaFuncSetAttribute(lin2,  cudaFuncAttributeMaxDynamicSharedMemorySize, L_SMEM);
        cudaFuncSetAttribute(attn2, cudaFuncAttributeMaxDynamicSharedMemorySize, A_SMEM);
        attr_done = 1;
    }

    const dim3 lin_grid(DD / 128, MM / 128);   // (4, 256)
    lin2<<<lin_grid, 256, L_SMEM>>>(x, Wk_w, pbrep, pK, 0);
    lin2<<<lin_grid, 256, L_SMEM>>>(x, Wv_w, pbrep, pV, 0);
    lin2<<<lin_grid, 256, L_SMEM>>>(x, Wq_w, pbrep, pQ, 0);

    expw_kernel<<<TT, 256>>>(w, pexpw);
    kmax_kernel<<<(TT * DD) / 256, 256>>>(pK, pKmax);
    ekv_kernel<<<(BB * TT * DD) / 256, 256>>>(pK, pV, pKmax, Wv_b);

    attn2<<<dim3(DD / 64, TT / 128, BB), 256, A_SMEM>>>(pexpw, pK, pV, pQ, Wq_b);

    brep_fill<<<(16 * DD) / 256, 256>>>(Wo_b, pbrep);
    lin2<<<lin_grid, 256, L_SMEM>>>(pQ, Wo_w, pbrep, out, 1);
}

// round 5
// speedup vs baseline: 1.8571x; 1.1382x over previous
#include <cuda_runtime.h>
#include <math.h>
#include <mma.h>
#include <stdint.h>

using namespace nvcuda;

#define BB 32
#define TT 1024
#define DD 512
#define MM (BB * TT)

// Scratch (__device__ globals; no allocations allowed)
__device__ float g_K[MM * DD];
__device__ float g_V[MM * DD];
__device__ float g_Q[MM * DD];
__device__ float g_Kmax[TT * DD];
__device__ float g_expw[TT * TT];
__device__ float g_brep[16 * DD];
__device__ float g_W3[3 * DD * DD];   // [Wk; Wv; Wq] rows

__device__ __forceinline__ uint32_t smem_u32(const void* p) {
    uint32_t a;
    asm("{ .reg .u64 t; cvta.to.shared.u64 t, %1; cvt.u32.u64 %0, t; }"
        : "=r"(a) : "l"(p));
    return a;
}

#define CP16(dst_f, src_f) \
    asm volatile("cp.async.cg.shared.global [%0], [%1], 16;" \
        :: "r"(smem_u32(dst_f)), "l"((const void*)(src_f)) : "memory")
#define CP_COMMIT() asm volatile("cp.async.commit_group;" ::: "memory")
#define CP_WAIT1()  asm volatile("cp.async.wait_group 1;" ::: "memory")

// ===========================================================================
// Linear NT GEMM (tf32 WMMA, warp tile 64x64, cp.async 3-stage)
//   C[m,n] = sum_k A[m,k] * W3[n,k]
// Block 128x128, 128 threads (4 warps 2x2), K-chunk 32.
// Fused mode (out==null): route output block to K/V/Q by n>>9.
// Final mode (out!=null): single output with bias from brep.
// ===========================================================================
#define L_STAGE 9216           // floats: As 128*36 + Bs 128*36
#define L_NST 3
#define L_SMEM (L_NST * L_STAGE * 4)

__global__ __launch_bounds__(128)
void lin3(const float* __restrict__ A, const float* __restrict__ W,
          const float* __restrict__ brep,
          float* __restrict__ K, float* __restrict__ V, float* __restrict__ Q,
          float* __restrict__ out)
{
    extern __shared__ float sm[];
    const int tid = threadIdx.x;
    const int wid = tid >> 5;
    const int wm = wid >> 1;          // 0..1 (64 rows)
    const int wn = wid & 1;           // 0..1 (64 cols)
    const int m0 = blockIdx.y * 128, n0 = blockIdx.x * 128;

    wmma::fragment<wmma::accumulator, 16, 16, 8, float> c[4][4];
#pragma unroll
    for (int i = 0; i < 4; i++)
#pragma unroll
        for (int j = 0; j < 4; j++) {
            if (out)
                wmma::load_matrix_sync(c[i][j],
                    brep + n0 + wn * 64 + j * 16, DD, wmma::mem_row_major);
            else
                wmma::fill_fragment(c[i][j], 0.0f);
        }

    auto issue = [&](int chunk, int st) {
        float* As = sm + st * L_STAGE;
        float* Bs = As + 4608;
        const int k0 = chunk * 32;
#pragma unroll
        for (int i = 0; i < 8; i++) {
            const int f = tid + i * 128;       // 0..1023
            const int row = f >> 3, c4 = f & 7;
            CP16(As + row * 36 + c4 * 4, A + (size_t)(m0 + row) * DD + k0 + c4 * 4);
            CP16(Bs + row * 36 + c4 * 4, W + (size_t)(n0 + row) * DD + k0 + c4 * 4);
        }
        CP_COMMIT();
    };

    issue(0, 0);
    issue(1, 1);

    const int NC = DD / 32;   // 16
    for (int ch = 0; ch < NC; ch++) {
        CP_WAIT1();
        __syncthreads();
        if (ch + 2 < NC) issue(ch + 2, (ch + 2) % L_NST);

        const float* As = sm + (ch % L_NST) * L_STAGE;
        const float* Bs = As + 4608;
#pragma unroll
        for (int kk = 0; kk < 4; kk++) {
            wmma::fragment<wmma::matrix_a, 16, 16, 8, wmma::precision::tf32, wmma::row_major> a[4];
            wmma::fragment<wmma::matrix_b, 16, 16, 8, wmma::precision::tf32, wmma::col_major> b[4];
#pragma unroll
            for (int i = 0; i < 4; i++)
                wmma::load_matrix_sync(a[i], As + (wm * 64 + i * 16) * 36 + kk * 8, 36);
#pragma unroll
            for (int j = 0; j < 4; j++)
                wmma::load_matrix_sync(b[j], Bs + (wn * 64 + j * 16) * 36 + kk * 8, 36);
#pragma unroll
            for (int i = 0; i < 4; i++)
#pragma unroll
                for (int j = 0; j < 4; j++)
                    wmma::mma_sync(c[i][j], a[i], b[j], c[i][j]);
        }
    }

    // Epilogue
    float* dst;
    int col0;
    if (out) { dst = out; col0 = n0; }
    else {
        const int mat = n0 >> 9;
        dst = (mat == 0) ? K : (mat == 1) ? V : Q;
        col0 = n0 & 511;
    }
#pragma unroll
    for (int i = 0; i < 4; i++)
#pragma unroll
        for (int j = 0; j < 4; j++)
            wmma::store_matrix_sync(dst + (size_t)(m0 + wm * 64 + i * 16) * DD
                                        + col0 + wn * 64 + j * 16,
                                    c[i][j], DD, wmma::mem_row_major);
}

// ===========================================================================
// Attention: num = expw @ EKV, den = expw @ EK (per batch),
// epilogue Q <- sigmoid(Q + bq) * num / den.
// Block 128(t) x 128(d), 256 threads (8 warps 2x4), warp 64x32 dual-acc.
// K(s)-chunk 32, 3-stage cp.async pipeline.
// ===========================================================================
#define A_STAGE 13056          // floats: Ws 128*36 + EK 32*132 + EKV 32*132
#define A_NST 3
#define A_SMEM (A_NST * A_STAGE * 4)

__global__ __launch_bounds__(256)
void attn3(const float* __restrict__ expw, const float* __restrict__ EK,
           const float* __restrict__ EKV, float* __restrict__ Q,
           const float* __restrict__ bq)
{
    extern __shared__ float sm[];
    const int tid = threadIdx.x;
    const int wid = tid >> 5;
    const int wm = wid >> 2;          // 0..1 (64 t-rows)
    const int wn = wid & 3;           // 0..3 (32 d-cols)
    const int d0 = blockIdx.x * 128, t0 = blockIdx.y * 128, b = blockIdx.z;

    const float* ekb  = EK  + (size_t)b * TT * DD;
    const float* ekvb = EKV + (size_t)b * TT * DD;

    wmma::fragment<wmma::accumulator, 16, 16, 8, float> cN[4][2], cD[4][2];
#pragma unroll
    for (int i = 0; i < 4; i++)
#pragma unroll
        for (int j = 0; j < 2; j++) {
            wmma::fill_fragment(cN[i][j], 0.0f);
            wmma::fill_fragment(cD[i][j], 0.0f);
        }

    auto issue = [&](int chunk, int st) {
        float* Ws  = sm + st * A_STAGE;
        float* EKs = Ws + 4608;
        float* EVs = EKs + 4224;
        const int s0 = chunk * 32;
#pragma unroll
        for (int i = 0; i < 4; i++) {       // Ws: 128x32 -> 1024 f4
            const int f = tid + i * 256;
            const int row = f >> 3, c4 = f & 7;
            CP16(Ws + row * 36 + c4 * 4, expw + (size_t)(t0 + row) * TT + s0 + c4 * 4);
        }
#pragma unroll
        for (int i = 0; i < 4; i++) {       // EK/EKV: 32x128 -> 1024 f4 each
            const int f = tid + i * 256;
            const int row = f >> 5, c4 = f & 31;
            CP16(EKs + row * 132 + c4 * 4, ekb  + (size_t)(s0 + row) * DD + d0 + c4 * 4);
            CP16(EVs + row * 132 + c4 * 4, ekvb + (size_t)(s0 + row) * DD + d0 + c4 * 4);
        }
        CP_COMMIT();
    };

    issue(0, 0);
    issue(1, 1);

    const int NC = TT / 32;   // 32
    for (int ch = 0; ch < NC; ch++) {
        CP_WAIT1();
        __syncthreads();
        if (ch + 2 < NC) issue(ch + 2, (ch + 2) % A_NST);

        const float* Ws  = sm + (ch % A_NST) * A_STAGE;
        const float* EKs = Ws + 4608;
        const float* EVs = EKs + 4224;
#pragma unroll
        for (int kk = 0; kk < 4; kk++) {
            wmma::fragment<wmma::matrix_a, 16, 16, 8, wmma::precision::tf32, wmma::row_major> a[4];
            wmma::fragment<wmma::matrix_b, 16, 16, 8, wmma::precision::tf32, wmma::row_major> bK[2], bV[2];
#pragma unroll
            for (int i = 0; i < 4; i++)
                wmma::load_matrix_sync(a[i], Ws + (wm * 64 + i * 16) * 36 + kk * 8, 36);
#pragma unroll
            for (int j = 0; j < 2; j++) {
                wmma::load_matrix_sync(bK[j], EKs + (kk * 8) * 132 + wn * 32 + j * 16, 132);
                wmma::load_matrix_sync(bV[j], EVs + (kk * 8) * 132 + wn * 32 + j * 16, 132);
            }
#pragma unroll
            for (int i = 0; i < 4; i++)
#pragma unroll
                for (int j = 0; j < 2; j++) {
                    wmma::mma_sync(cN[i][j], a[i], bV[j], cN[i][j]);
                    wmma::mma_sync(cD[i][j], a[i], bK[j], cD[i][j]);
                }
        }
    }

    // Epilogue: stage num/den in smem, apply sigmoid(Q+bq)*num/den
    __syncthreads();
    float* num = sm;                   // [128][132]
    float* den = sm + 128 * 132;       // [128][132]
#pragma unroll
    for (int i = 0; i < 4; i++)
#pragma unroll
        for (int j = 0; j < 2; j++) {
            wmma::store_matrix_sync(&num[(wm * 64 + i * 16) * 132 + wn * 32 + j * 16],
                                    cN[i][j], 132, wmma::mem_row_major);
            wmma::store_matrix_sync(&den[(wm * 64 + i * 16) * 132 + wn * 32 + j * 16],
                                    cD[i][j], 132, wmma::mem_row_major);
        }
    __syncthreads();

#pragma unroll
    for (int it = 0; it < 16; it++) {
        const int f = tid + it * 256;        // 0..4095 f4 over 128x128
        const int row = f >> 5, c4 = f & 31;
        const size_t qidx = ((size_t)b * TT + t0 + row) * DD + d0 + c4 * 4;
        float4 q = *(const float4*)(Q + qidx);
        float4 b4 = __ldg((const float4*)(bq + d0 + c4 * 4));
        const float* np = &num[row * 132 + c4 * 4];
        const float* dp = &den[row * 132 + c4 * 4];
        float4 o;
        o.x = (1.f / (1.f + expf(-(q.x + b4.x)))) * np[0] / dp[0];
        o.y = (1.f / (1.f + expf(-(q.y + b4.y)))) * np[1] / dp[1];
        o.z = (1.f / (1.f + expf(-(q.z + b4.z)))) * np[2] / dp[2];
        o.w = (1.f / (1.f + expf(-(q.w + b4.w)))) * np[3] / dp[3];
        *(float4*)(Q + qidx) = o;
    }
}

// ===========================================================================
// Elementwise kernels
// ===========================================================================
__global__ __launch_bounds__(256)
void expw_kernel(const float* __restrict__ w, float* __restrict__ ew)
{
    const int t = blockIdx.x;
    const float* row = w + (size_t)t * TT;
    float m = -INFINITY;
    for (int i = threadIdx.x; i < TT; i += 256) m = fmaxf(m, row[i]);
#pragma unroll
    for (int o = 16; o > 0; o >>= 1) m = fmaxf(m, __shfl_xor_sync(0xffffffffu, m, o));
    __shared__ float warpmax[8];
    __shared__ float rowmax;
    if ((threadIdx.x & 31) == 0) warpmax[threadIdx.x >> 5] = m;
    __syncthreads();
    if (threadIdx.x == 0) {
        float mm = warpmax[0];
#pragma unroll
        for (int i = 1; i < 8; i++) mm = fmaxf(mm, warpmax[i]);
        rowmax = mm;
    }
    __syncthreads();
    const float rm = rowmax;
    for (int i = threadIdx.x; i < TT; i += 256)
        ew[(size_t)t * TT + i] = expf(row[i] - rm);
}

__global__ __launch_bounds__(256)
void kmax_kernel(const float* __restrict__ K, float* __restrict__ Kmax)
{
    const int idx = blockIdx.x * 256 + threadIdx.x;
    float m = -INFINITY;
#pragma unroll 4
    for (int b = 0; b < BB; b++)
        m = fmaxf(m, K[(size_t)b * TT * DD + idx]);
    Kmax[idx] = m;
}

__global__ __launch_bounds__(256)
void ekv_kernel(float* __restrict__ K, float* __restrict__ V,
                const float* __restrict__ Kmax, const float* __restrict__ bv)
{
    const size_t idx = (size_t)blockIdx.x * 256 + threadIdx.x;
    const float ek = expf(K[idx] - Kmax[idx & (size_t)(TT * DD - 1)]);
    K[idx] = ek;
    V[idx] = ek * (V[idx] + bv[idx & (DD - 1)]);
}

__global__ void brep_fill(const float* __restrict__ bo, float* __restrict__ brep)
{
    const int idx = blockIdx.x * 256 + threadIdx.x;
    brep[idx] = bo[idx & (DD - 1)];
}

// Concatenate [Wk; Wv; Wq] into g_W3 (float4 copies)
__global__ void wcat_kernel(const float* __restrict__ Wk,
                            const float* __restrict__ Wv,
                            const float* __restrict__ Wq,
                            float* __restrict__ W3)
{
    const int f = blockIdx.x * 256 + threadIdx.x;   // f4 index < 3*512*512/4
    const int per = DD * DD / 4;                     // 65536
    const float* src = (f < per) ? Wk : (f < 2 * per) ? Wv : Wq;
    const int off = f % per;
    ((float4*)W3)[f] = ((const float4*)src)[off];
}

// ===========================================================================
extern "C" void kernel_launch(void* const* d_in, const int* in_sizes, int n_in,
                              void* d_out, int out_size)
{
    const float* x    = (const float*)d_in[0];
    const float* Wk_w = (const float*)d_in[1];
    // Wk_b unused: K bias cancels inside exp(K - max_b K)
    const float* Wv_w = (const float*)d_in[3];
    const float* Wv_b = (const float*)d_in[4];
    const float* Wq_w = (const float*)d_in[5];
    const float* Wq_b = (const float*)d_in[6];
    const float* w    = (const float*)d_in[7];
    const float* Wo_w = (const float*)d_in[8];
    const float* Wo_b = (const float*)d_in[9];
    float* out = (float*)d_out;

    float *pK, *pV, *pQ, *pKmax, *pexpw, *pbrep, *pW3;
    cudaGetSymbolAddress((void**)&pK, g_K);
    cudaGetSymbolAddress((void**)&pV, g_V);
    cudaGetSymbolAddress((void**)&pQ, g_Q);
    cudaGetSymbolAddress((void**)&pKmax, g_Kmax);
    cudaGetSymbolAddress((void**)&pexpw, g_expw);
    cudaGetSymbolAddress((void**)&pbrep, g_brep);
    cudaGetSymbolAddress((void**)&pW3, g_W3);

    cudaFuncSetAttribute(lin3,  cudaFuncAttributeMaxDynamicSharedMemorySize, L_SMEM);
    cudaFuncSetAttribute(attn3, cudaFuncAttributeMaxDynamicSharedMemorySize, A_SMEM);

    // Cheap prep first (also shifts GEMMs into the profiler's capture slot)
    expw_kernel<<<TT, 256>>>(w, pexpw);
    wcat_kernel<<<(3 * DD * DD / 4) / 256, 256>>>(Wk_w, Wv_w, Wq_w, pW3);
    brep_fill<<<(16 * DD) / 256, 256>>>(Wo_b, pbrep);

    // Fused K/V/Q linear: N = 1536
    lin3<<<dim3(12, MM / 128), 128, L_SMEM>>>(x, pW3, pbrep, pK, pV, pQ, nullptr);

    kmax_kernel<<<(TT * DD) / 256, 256>>>(pK, pKmax);
    ekv_kernel<<<(BB * TT * DD) / 256, 256>>>(pK, pV, pKmax, Wv_b);

    attn3<<<dim3(DD / 128, TT / 128, BB), 256, A_SMEM>>>(pexpw, pK, pV, pQ, Wq_b);

    // Final linear with bias
    lin3<<<dim3(4, MM / 128), 128, L_SMEM>>>(pQ, Wo_w, pbrep, nullptr, nullptr, nullptr, out);
}

// round 6
// speedup vs baseline: 3.3203x; 1.7879x over previous
#include <cuda_runtime.h>
#include <cuda_fp16.h>
#include <math.h>
#include <mma.h>
#include <stdint.h>

using namespace nvcuda;

#define BB 32
#define TT 1024
#define DD 512
#define MM (BB * TT)

// Scratch (__device__ globals; no allocations allowed)
__device__ float  g_K[MM * DD];
__device__ float  g_V[MM * DD];
__device__ float  g_Q[MM * DD];
__device__ float  g_Kmax[TT * DD];
__device__ float  g_brep[16 * DD];
__device__ __half g_xh[MM * DD];
__device__ __half g_W3h[3 * DD * DD];
__device__ __half g_Woh[DD * DD];
__device__ __half g_expwh[TT * TT];
__device__ __half g_EKh[MM * DD];
__device__ __half g_EKVh[MM * DD];
__device__ __half g_Yth[MM * DD];

__device__ __forceinline__ uint32_t smem_u32(const void* p) {
    uint32_t a;
    asm("{ .reg .u64 t; cvta.to.shared.u64 t, %1; cvt.u32.u64 %0, t; }"
        : "=r"(a) : "l"(p));
    return a;
}

#define CP16(dst, src) \
    asm volatile("cp.async.cg.shared.global [%0], [%1], 16;" \
        :: "r"(smem_u32(dst)), "l"((const void*)(src)) : "memory")
#define CP_COMMIT() asm volatile("cp.async.commit_group;" ::: "memory")
#define CP_WAIT1()  asm volatile("cp.async.wait_group 1;" ::: "memory")

// ===========================================================================
// Linear NT GEMM (fp16 WMMA 16x16x16, fp32 acc, cp.async 3-stage)
//   C[m,n] = sum_k A[m,k] * W[n,k]
// Block 128(M)x256(N), 256 threads, 8 warps (2Mx4N), warp tile 64x64.
// K-chunk 32 (2 ksteps). Fused mode (out==null): route to K/V/Q by n>>9.
// ===========================================================================
#define L_STAGE 15360   // halves: As 128*40 + Bs 256*40
#define L_NST 3
#define L_SMEM (L_NST * L_STAGE * 2)   // 92160 B

__global__ __launch_bounds__(256)
void linh(const __half* __restrict__ A, const __half* __restrict__ W,
          const float* __restrict__ brep,
          float* __restrict__ K, float* __restrict__ V, float* __restrict__ Q,
          float* __restrict__ out)
{
    extern __shared__ __half sh[];
    const int tid = threadIdx.x;
    const int wid = tid >> 5;
    const int wm = wid >> 2;          // 0..1 (64 rows)
    const int wn = wid & 3;           // 0..3 (64 cols)
    const int m0 = blockIdx.y * 128, n0 = blockIdx.x * 256;

    wmma::fragment<wmma::accumulator, 16, 16, 16, float> c[4][4];
#pragma unroll
    for (int i = 0; i < 4; i++)
#pragma unroll
        for (int j = 0; j < 4; j++) {
            if (out)
                wmma::load_matrix_sync(c[i][j],
                    brep + ((n0 + wn * 64 + j * 16) & (DD - 1)),
                    DD, wmma::mem_row_major);
            else
                wmma::fill_fragment(c[i][j], 0.0f);
        }

    auto issue = [&](int chunk, int st) {
        __half* As = sh + st * L_STAGE;
        __half* Bs = As + 128 * 40;
        const int k0 = chunk * 32;
#pragma unroll
        for (int i = 0; i < 2; i++) {          // As: 512 cp16
            const int f = tid + i * 256;
            const int row = f >> 2, c8 = f & 3;
            CP16(As + row * 40 + c8 * 8, A + (size_t)(m0 + row) * DD + k0 + c8 * 8);
        }
#pragma unroll
        for (int i = 0; i < 4; i++) {          // Bs: 1024 cp16
            const int f = tid + i * 256;
            const int row = f >> 2, c8 = f & 3;
            CP16(Bs + row * 40 + c8 * 8, W + (size_t)(n0 + row) * DD + k0 + c8 * 8);
        }
        CP_COMMIT();
    };

    issue(0, 0);
    issue(1, 1);

    const int NC = DD / 32;   // 16
    for (int ch = 0; ch < NC; ch++) {
        CP_WAIT1();
        __syncthreads();
        if (ch + 2 < NC) issue(ch + 2, (ch + 2) % L_NST);

        const __half* As = sh + (ch % L_NST) * L_STAGE;
        const __half* Bs = As + 128 * 40;
#pragma unroll
        for (int kk = 0; kk < 2; kk++) {
            wmma::fragment<wmma::matrix_a, 16, 16, 16, __half, wmma::row_major> a[4];
            wmma::fragment<wmma::matrix_b, 16, 16, 16, __half, wmma::col_major> b[4];
#pragma unroll
            for (int i = 0; i < 4; i++)
                wmma::load_matrix_sync(a[i], As + (wm * 64 + i * 16) * 40 + kk * 16, 40);
#pragma unroll
            for (int j = 0; j < 4; j++)
                wmma::load_matrix_sync(b[j], Bs + (wn * 64 + j * 16) * 40 + kk * 16, 40);
#pragma unroll
            for (int i = 0; i < 4; i++)
#pragma unroll
                for (int j = 0; j < 4; j++)
                    wmma::mma_sync(c[i][j], a[i], b[j], c[i][j]);
        }
    }

    // Epilogue: direct fp32 store with K/V/Q routing
    float* dst;
    int col0;
    if (out) { dst = out; col0 = n0; }
    else {
        const int mat = n0 >> 9;
        dst = (mat == 0) ? K : (mat == 1) ? V : Q;
        col0 = n0 & 511;
    }
#pragma unroll
    for (int i = 0; i < 4; i++)
#pragma unroll
        for (int j = 0; j < 4; j++)
            wmma::store_matrix_sync(dst + (size_t)(m0 + wm * 64 + i * 16) * DD
                                        + col0 + wn * 64 + j * 16,
                                    c[i][j], DD, wmma::mem_row_major);
}

// ===========================================================================
// Attention (fp16 WMMA): num = expw @ EKV, den = expw @ EK per batch,
// epilogue Yt_h <- half( sigmoid(Q + bq) * num / den ).
// Block 128(t)x128(d), 256 threads, 8 warps (2x4), warp 64x32 dual-acc.
// ===========================================================================
#define A_STAGE 13824   // halves: Ws 128*40 + EK 32*136 + EKV 32*136
#define A_NST 3
#define A_SMEM_BYTES 135168   // max(3*A_STAGE*2 = 82944, epi 2*128*132*4)

__global__ __launch_bounds__(256)
void attnh(const __half* __restrict__ expw, const __half* __restrict__ EK,
           const __half* __restrict__ EKV, const float* __restrict__ Q,
           const float* __restrict__ bq, __half* __restrict__ Yt)
{
    extern __shared__ __half sh[];
    const int tid = threadIdx.x;
    const int wid = tid >> 5;
    const int wm = wid >> 2;          // 0..1 (64 t-rows)
    const int wn = wid & 3;           // 0..3 (32 d-cols)
    const int d0 = blockIdx.x * 128, t0 = blockIdx.y * 128, b = blockIdx.z;

    const __half* ekb  = EK  + (size_t)b * TT * DD;
    const __half* ekvb = EKV + (size_t)b * TT * DD;

    wmma::fragment<wmma::accumulator, 16, 16, 16, float> cN[4][2], cD[4][2];
#pragma unroll
    for (int i = 0; i < 4; i++)
#pragma unroll
        for (int j = 0; j < 2; j++) {
            wmma::fill_fragment(cN[i][j], 0.0f);
            wmma::fill_fragment(cD[i][j], 0.0f);
        }

    auto issue = [&](int chunk, int st) {
        __half* Ws  = sh + st * A_STAGE;
        __half* EKs = Ws + 128 * 40;
        __half* EVs = EKs + 32 * 136;
        const int s0 = chunk * 32;
#pragma unroll
        for (int i = 0; i < 2; i++) {          // Ws: 128x32 -> 512 cp16
            const int f = tid + i * 256;
            const int row = f >> 2, c8 = f & 3;
            CP16(Ws + row * 40 + c8 * 8, expw + (size_t)(t0 + row) * TT + s0 + c8 * 8);
        }
#pragma unroll
        for (int i = 0; i < 2; i++) {          // EK/EKV: 32x128 -> 512 cp16 each
            const int f = tid + i * 256;
            const int row = f >> 4, c8 = f & 15;
            CP16(EKs + row * 136 + c8 * 8, ekb  + (size_t)(s0 + row) * DD + d0 + c8 * 8);
            CP16(EVs + row * 136 + c8 * 8, ekvb + (size_t)(s0 + row) * DD + d0 + c8 * 8);
        }
        CP_COMMIT();
    };

    issue(0, 0);
    issue(1, 1);

    const int NC = TT / 32;   // 32
    for (int ch = 0; ch < NC; ch++) {
        CP_WAIT1();
        __syncthreads();
        if (ch + 2 < NC) issue(ch + 2, (ch + 2) % A_NST);

        const __half* Ws  = sh + (ch % A_NST) * A_STAGE;
        const __half* EKs = Ws + 128 * 40;
        const __half* EVs = EKs + 32 * 136;
#pragma unroll
        for (int kk = 0; kk < 2; kk++) {
            wmma::fragment<wmma::matrix_a, 16, 16, 16, __half, wmma::row_major> a[4];
            wmma::fragment<wmma::matrix_b, 16, 16, 16, __half, wmma::row_major> bK[2], bV[2];
#pragma unroll
            for (int i = 0; i < 4; i++)
                wmma::load_matrix_sync(a[i], Ws + (wm * 64 + i * 16) * 40 + kk * 16, 40);
#pragma unroll
            for (int j = 0; j < 2; j++) {
                wmma::load_matrix_sync(bK[j], EKs + (kk * 16) * 136 + wn * 32 + j * 16, 136);
                wmma::load_matrix_sync(bV[j], EVs + (kk * 16) * 136 + wn * 32 + j * 16, 136);
            }
#pragma unroll
            for (int i = 0; i < 4; i++)
#pragma unroll
                for (int j = 0; j < 2; j++) {
                    wmma::mma_sync(cN[i][j], a[i], bV[j], cN[i][j]);
                    wmma::mma_sync(cD[i][j], a[i], bK[j], cD[i][j]);
                }
        }
    }

    // Epilogue
    __syncthreads();
    float* num = (float*)sh;           // [128][132]
    float* den = num + 128 * 132;      // [128][132]
#pragma unroll
    for (int i = 0; i < 4; i++)
#pragma unroll
        for (int j = 0; j < 2; j++) {
            wmma::store_matrix_sync(&num[(wm * 64 + i * 16) * 132 + wn * 32 + j * 16],
                                    cN[i][j], 132, wmma::mem_row_major);
            wmma::store_matrix_sync(&den[(wm * 64 + i * 16) * 132 + wn * 32 + j * 16],
                                    cD[i][j], 132, wmma::mem_row_major);
        }
    __syncthreads();

#pragma unroll
    for (int it = 0; it < 16; it++) {
        const int f = tid + it * 256;        // 0..4095 f4 over 128x128
        const int row = f >> 5, c4 = f & 31;
        const size_t qidx = ((size_t)b * TT + t0 + row) * DD + d0 + c4 * 4;
        float4 q = *(const float4*)(Q + qidx);
        float4 b4 = __ldg((const float4*)(bq + d0 + c4 * 4));
        const float* np = &num[row * 132 + c4 * 4];
        const float* dp = &den[row * 132 + c4 * 4];
        float ox = (1.f / (1.f + expf(-(q.x + b4.x)))) * np[0] / dp[0];
        float oy = (1.f / (1.f + expf(-(q.y + b4.y)))) * np[1] / dp[1];
        float oz = (1.f / (1.f + expf(-(q.z + b4.z)))) * np[2] / dp[2];
        float ow = (1.f / (1.f + expf(-(q.w + b4.w)))) * np[3] / dp[3];
        __half2* yp = (__half2*)(Yt + qidx);
        yp[0] = __floats2half2_rn(ox, oy);
        yp[1] = __floats2half2_rn(oz, ow);
    }
}

// ===========================================================================
// Elementwise / conversion kernels
// ===========================================================================
__global__ __launch_bounds__(256)
void expw_kernel(const float* __restrict__ w, __half* __restrict__ ew)
{
    const int t = blockIdx.x;
    const float* row = w + (size_t)t * TT;
    float m = -INFINITY;
    for (int i = threadIdx.x; i < TT; i += 256) m = fmaxf(m, row[i]);
#pragma unroll
    for (int o = 16; o > 0; o >>= 1) m = fmaxf(m, __shfl_xor_sync(0xffffffffu, m, o));
    __shared__ float warpmax[8];
    __shared__ float rowmax;
    if ((threadIdx.x & 31) == 0) warpmax[threadIdx.x >> 5] = m;
    __syncthreads();
    if (threadIdx.x == 0) {
        float mm = warpmax[0];
#pragma unroll
        for (int i = 1; i < 8; i++) mm = fmaxf(mm, warpmax[i]);
        rowmax = mm;
    }
    __syncthreads();
    const float rm = rowmax;
    for (int i = threadIdx.x; i < TT; i += 256)
        ew[(size_t)t * TT + i] = __float2half(expf(row[i] - rm));
}

__global__ __launch_bounds__(256)
void kmax_kernel(const float* __restrict__ K, float* __restrict__ Kmax)
{
    const int idx = blockIdx.x * 256 + threadIdx.x;
    float m = -INFINITY;
#pragma unroll 4
    for (int b = 0; b < BB; b++)
        m = fmaxf(m, K[(size_t)b * TT * DD + idx]);
    Kmax[idx] = m;
}

__global__ __launch_bounds__(256)
void ekv_kernel(const float* __restrict__ K, const float* __restrict__ V,
                const float* __restrict__ Kmax, const float* __restrict__ bv,
                __half* __restrict__ EK, __half* __restrict__ EKV)
{
    const size_t idx = (size_t)blockIdx.x * 256 + threadIdx.x;
    const float ek = expf(K[idx] - Kmax[idx & (size_t)(TT * DD - 1)]);
    EK[idx]  = __float2half(ek);
    EKV[idx] = __float2half(ek * (V[idx] + bv[idx & (DD - 1)]));
}

__global__ void brep_fill(const float* __restrict__ bo, float* __restrict__ brep)
{
    const int idx = blockIdx.x * 256 + threadIdx.x;
    brep[idx] = bo[idx & (DD - 1)];
}

// x fp32 -> half (float4 granularity)
__global__ __launch_bounds__(256)
void f2h_kernel(const float* __restrict__ src, __half* __restrict__ dst)
{
    const size_t f = (size_t)blockIdx.x * 256 + threadIdx.x;   // f4 index
    float4 v = ((const float4*)src)[f];
    __half2* d = (__half2*)(dst + f * 4);
    d[0] = __floats2half2_rn(v.x, v.y);
    d[1] = __floats2half2_rn(v.z, v.w);
}

// Convert Wk/Wv/Wq -> W3h and Wo -> Woh
__global__ __launch_bounds__(256)
void wconv_kernel(const float* __restrict__ Wk, const float* __restrict__ Wv,
                  const float* __restrict__ Wq, const float* __restrict__ Wo,
                  __half* __restrict__ W3h, __half* __restrict__ Woh)
{
    const int f = blockIdx.x * 256 + threadIdx.x;    // f4 index < 4*65536
    const int per = DD * DD / 4;
    const float* src; __half* dst; int off;
    if (f < per)           { src = Wk; dst = W3h;            off = f; }
    else if (f < 2 * per)  { src = Wv; dst = W3h + DD * DD;  off = f - per; }
    else if (f < 3 * per)  { src = Wq; dst = W3h + 2*DD*DD;  off = f - 2 * per; }
    else                   { src = Wo; dst = Woh;            off = f - 3 * per; }
    float4 v = ((const float4*)src)[off];
    __half2* d = (__half2*)(dst + (size_t)off * 4);
    d[0] = __floats2half2_rn(v.x, v.y);
    d[1] = __floats2half2_rn(v.z, v.w);
}

// ===========================================================================
extern "C" void kernel_launch(void* const* d_in, const int* in_sizes, int n_in,
                              void* d_out, int out_size)
{
    const float* x    = (const float*)d_in[0];
    const float* Wk_w = (const float*)d_in[1];
    // Wk_b unused: K bias cancels inside exp(K - max_b K)
    const float* Wv_w = (const float*)d_in[3];
    const float* Wv_b = (const float*)d_in[4];
    const float* Wq_w = (const float*)d_in[5];
    const float* Wq_b = (const float*)d_in[6];
    const float* w    = (const float*)d_in[7];
    const float* Wo_w = (const float*)d_in[8];
    const float* Wo_b = (const float*)d_in[9];
    float* out = (float*)d_out;

    float *pK, *pV, *pQ, *pKmax, *pbrep;
    __half *pxh, *pW3h, *pWoh, *pexpwh, *pEKh, *pEKVh, *pYth;
    cudaGetSymbolAddress((void**)&pK, g_K);
    cudaGetSymbolAddress((void**)&pV, g_V);
    cudaGetSymbolAddress((void**)&pQ, g_Q);
    cudaGetSymbolAddress((void**)&pKmax, g_Kmax);
    cudaGetSymbolAddress((void**)&pbrep, g_brep);
    cudaGetSymbolAddress((void**)&pxh, g_xh);
    cudaGetSymbolAddress((void**)&pW3h, g_W3h);
    cudaGetSymbolAddress((void**)&pWoh, g_Woh);
    cudaGetSymbolAddress((void**)&pexpwh, g_expwh);
    cudaGetSymbolAddress((void**)&pEKh, g_EKh);
    cudaGetSymbolAddress((void**)&pEKVh, g_EKVh);
    cudaGetSymbolAddress((void**)&pYth, g_Yth);

    cudaFuncSetAttribute(linh,  cudaFuncAttributeMaxDynamicSharedMemorySize, L_SMEM);
    cudaFuncSetAttribute(attnh, cudaFuncAttributeMaxDynamicSharedMemorySize, A_SMEM_BYTES);

    // Prep / conversions
    expw_kernel<<<TT, 256>>>(w, pexpwh);
    f2h_kernel<<<(MM * DD / 4) / 256, 256>>>(x, pxh);
    wconv_kernel<<<(4 * DD * DD / 4) / 256, 256>>>(Wk_w, Wv_w, Wq_w, Wo_w, pW3h, pWoh);
    brep_fill<<<(16 * DD) / 256, 256>>>(Wo_b, pbrep);

    // Fused K/V/Q linear: N = 1536 -> grid (6, 256)
    linh<<<dim3(6, MM / 128), 256, L_SMEM>>>(pxh, pW3h, pbrep, pK, pV, pQ, nullptr);

    kmax_kernel<<<(TT * DD) / 256, 256>>>(pK, pKmax);
    ekv_kernel<<<(BB * TT * DD) / 256, 256>>>(pK, pV, pKmax, Wv_b, pEKh, pEKVh);

    attnh<<<dim3(DD / 128, TT / 128, BB), 256, A_SMEM_BYTES>>>(pexpwh, pEKh, pEKVh, pQ, Wq_b, pYth);

    // Final linear with bias: N = 512 -> grid (2, 256)
    linh<<<dim3(2, MM / 128), 256, L_SMEM>>>(pYth, pWoh, pbrep, nullptr, nullptr, nullptr, out);
}

// round 7
// speedup vs baseline: 4.1194x; 1.2407x over previous
#include <cuda_runtime.h>
#include <cuda_fp16.h>
#include <math.h>
#include <mma.h>
#include <stdint.h>

using namespace nvcuda;

#define BB 32
#define TT 1024
#define DD 512
#define MM (BB * TT)

// Scratch (__device__ globals; no allocations allowed)
__device__ float  g_K[MM * DD];
__device__ float  g_V[MM * DD];
__device__ float  g_Q[MM * DD];
__device__ float  g_Kmax[TT * DD];
__device__ float  g_brep[16 * DD];
__device__ __half g_xh[MM * DD];
__device__ __half g_W3h[3 * DD * DD];
__device__ __half g_Woh[DD * DD];
__device__ __half g_expwh[TT * TT];
__device__ __half g_EKh[MM * DD];
__device__ __half g_EKVh[MM * DD];
__device__ __half g_Yth[MM * DD];

__device__ __forceinline__ uint32_t smem_u32(const void* p) {
    uint32_t a;
    asm("{ .reg .u64 t; cvta.to.shared.u64 t, %1; cvt.u32.u64 %0, t; }"
        : "=r"(a) : "l"(p));
    return a;
}

#define CP16(dst, src) \
    asm volatile("cp.async.cg.shared.global [%0], [%1], 16;" \
        :: "r"(smem_u32(dst)), "l"((const void*)(src)) : "memory")
#define CP_COMMIT() asm volatile("cp.async.commit_group;" ::: "memory")
#define CP_WAIT0()  asm volatile("cp.async.wait_group 0;" ::: "memory")
#define CP_WAIT1()  asm volatile("cp.async.wait_group 1;" ::: "memory")
#define CP_WAIT2()  asm volatile("cp.async.wait_group 2;" ::: "memory")

// ===========================================================================
// Linear NT GEMM (fp16 WMMA 16x16x16, fp32 acc, 4-stage cp.async, 3 in flight)
//   C[m,n] = sum_k A[m,k] * W[n,k]
// Block 128x128, 128 threads, 4 warps (2x2), warp tile 64x64. K-chunk 32.
// Fused mode (out==null): route output block to K/V/Q by n>>9.
// ===========================================================================
#define L_STAGE 10240   // halves per stage: As 128*40 + Bs 128*40
#define L_NST 4
#define L_SMEM (L_NST * L_STAGE * 2)   // 81920 B

__global__ __launch_bounds__(128)
void linh(const __half* __restrict__ A, const __half* __restrict__ W,
          const float* __restrict__ brep,
          float* __restrict__ K, float* __restrict__ V, float* __restrict__ Q,
          float* __restrict__ out)
{
    extern __shared__ __half sh[];
    const int tid = threadIdx.x;
    const int wid = tid >> 5;
    const int wm = wid >> 1;          // 0..1 (64 rows)
    const int wn = wid & 1;           // 0..1 (64 cols)
    const int m0 = blockIdx.y * 128, n0 = blockIdx.x * 128;

    wmma::fragment<wmma::accumulator, 16, 16, 16, float> c[4][4];
#pragma unroll
    for (int i = 0; i < 4; i++)
#pragma unroll
        for (int j = 0; j < 4; j++) {
            if (out)
                wmma::load_matrix_sync(c[i][j],
                    brep + ((n0 + wn * 64 + j * 16) & (DD - 1)),
                    DD, wmma::mem_row_major);
            else
                wmma::fill_fragment(c[i][j], 0.0f);
        }

    auto issue = [&](int chunk) {
        __half* As = sh + (chunk & (L_NST - 1)) * L_STAGE;
        __half* Bs = As + 128 * 40;
        const int k0 = chunk * 32;
#pragma unroll
        for (int i = 0; i < 4; i++) {          // As: 512 cp16
            const int f = tid + i * 128;
            const int row = f >> 2, c8 = f & 3;
            CP16(As + row * 40 + c8 * 8, A + (size_t)(m0 + row) * DD + k0 + c8 * 8);
        }
#pragma unroll
        for (int i = 0; i < 4; i++) {          // Bs: 512 cp16
            const int f = tid + i * 128;
            const int row = f >> 2, c8 = f & 3;
            CP16(Bs + row * 40 + c8 * 8, W + (size_t)(n0 + row) * DD + k0 + c8 * 8);
        }
        CP_COMMIT();
    };

    issue(0); issue(1); issue(2);

    const int NC = DD / 32;   // 16
    for (int ch = 0; ch < NC; ch++) {
        if (ch <= NC - 3)      CP_WAIT2();
        else if (ch == NC - 2) CP_WAIT1();
        else                   CP_WAIT0();
        __syncthreads();
        if (ch + 3 < NC) issue(ch + 3);

        const __half* As = sh + (ch & (L_NST - 1)) * L_STAGE;
        const __half* Bs = As + 128 * 40;
#pragma unroll
        for (int kk = 0; kk < 2; kk++) {
            wmma::fragment<wmma::matrix_a, 16, 16, 16, __half, wmma::row_major> a[4];
            wmma::fragment<wmma::matrix_b, 16, 16, 16, __half, wmma::col_major> b[4];
#pragma unroll
            for (int i = 0; i < 4; i++)
                wmma::load_matrix_sync(a[i], As + (wm * 64 + i * 16) * 40 + kk * 16, 40);
#pragma unroll
            for (int j = 0; j < 4; j++)
                wmma::load_matrix_sync(b[j], Bs + (wn * 64 + j * 16) * 40 + kk * 16, 40);
#pragma unroll
            for (int i = 0; i < 4; i++)
#pragma unroll
                for (int j = 0; j < 4; j++)
                    wmma::mma_sync(c[i][j], a[i], b[j], c[i][j]);
        }
    }

    float* dst;
    int col0;
    if (out) { dst = out; col0 = n0; }
    else {
        const int mat = n0 >> 9;
        dst = (mat == 0) ? K : (mat == 1) ? V : Q;
        col0 = n0 & 511;
    }
#pragma unroll
    for (int i = 0; i < 4; i++)
#pragma unroll
        for (int j = 0; j < 4; j++)
            wmma::store_matrix_sync(dst + (size_t)(m0 + wm * 64 + i * 16) * DD
                                        + col0 + wn * 64 + j * 16,
                                    c[i][j], DD, wmma::mem_row_major);
}

// ===========================================================================
// Attention (fp16 WMMA): num = expw @ EKV, den = expw @ EK per batch,
// epilogue Yt_h <- half( sigmoid(Q + bq) * num / den ).
// Block 64(t) x 64(d), 128 threads, 4 warps (2x2), warp 32x32 dual-acc.
// 4-stage cp.async pipeline, K(s)-chunk 32.
// ===========================================================================
#define A_STAGE 7168    // halves: Ws 64*40 + EK 32*72 + EKV 32*72
#define A_NST 4
#define A_SMEM (A_NST * A_STAGE * 2)   // 57344 B (epi needs 64*68*2*4 = 34816 B)

__global__ __launch_bounds__(128)
void attnh(const __half* __restrict__ expw, const __half* __restrict__ EK,
           const __half* __restrict__ EKV, const float* __restrict__ Q,
           const float* __restrict__ bq, __half* __restrict__ Yt)
{
    extern __shared__ __half sh[];
    const int tid = threadIdx.x;
    const int wid = tid >> 5;
    const int wm = wid >> 1;          // 0..1 (32 t-rows)
    const int wn = wid & 1;           // 0..1 (32 d-cols)
    const int d0 = blockIdx.x * 64, t0 = blockIdx.y * 64, b = blockIdx.z;

    const __half* ekb  = EK  + (size_t)b * TT * DD;
    const __half* ekvb = EKV + (size_t)b * TT * DD;

    wmma::fragment<wmma::accumulator, 16, 16, 16, float> cN[2][2], cD[2][2];
#pragma unroll
    for (int i = 0; i < 2; i++)
#pragma unroll
        for (int j = 0; j < 2; j++) {
            wmma::fill_fragment(cN[i][j], 0.0f);
            wmma::fill_fragment(cD[i][j], 0.0f);
        }

    auto issue = [&](int chunk) {
        __half* Ws  = sh + (chunk & (A_NST - 1)) * A_STAGE;
        __half* EKs = Ws + 64 * 40;
        __half* EVs = EKs + 32 * 72;
        const int s0 = chunk * 32;
#pragma unroll
        for (int i = 0; i < 2; i++) {          // Ws: 64x32 -> 256 cp16
            const int f = tid + i * 128;
            const int row = f >> 2, c8 = f & 3;
            CP16(Ws + row * 40 + c8 * 8, expw + (size_t)(t0 + row) * TT + s0 + c8 * 8);
        }
#pragma unroll
        for (int i = 0; i < 2; i++) {          // EK/EKV: 32x64 -> 256 cp16 each
            const int f = tid + i * 128;
            const int row = f >> 3, c8 = f & 7;
            CP16(EKs + row * 72 + c8 * 8, ekb  + (size_t)(s0 + row) * DD + d0 + c8 * 8);
            CP16(EVs + row * 72 + c8 * 8, ekvb + (size_t)(s0 + row) * DD + d0 + c8 * 8);
        }
        CP_COMMIT();
    };

    issue(0); issue(1); issue(2);

    const int NC = TT / 32;   // 32
    for (int ch = 0; ch < NC; ch++) {
        if (ch <= NC - 3)      CP_WAIT2();
        else if (ch == NC - 2) CP_WAIT1();
        else                   CP_WAIT0();
        __syncthreads();
        if (ch + 3 < NC) issue(ch + 3);

        const __half* Ws  = sh + (ch & (A_NST - 1)) * A_STAGE;
        const __half* EKs = Ws + 64 * 40;
        const __half* EVs = EKs + 32 * 72;
#pragma unroll
        for (int kk = 0; kk < 2; kk++) {
            wmma::fragment<wmma::matrix_a, 16, 16, 16, __half, wmma::row_major> a[2];
            wmma::fragment<wmma::matrix_b, 16, 16, 16, __half, wmma::row_major> bK[2], bV[2];
#pragma unroll
            for (int i = 0; i < 2; i++)
                wmma::load_matrix_sync(a[i], Ws + (wm * 32 + i * 16) * 40 + kk * 16, 40);
#pragma unroll
            for (int j = 0; j < 2; j++) {
                wmma::load_matrix_sync(bK[j], EKs + (kk * 16) * 72 + wn * 32 + j * 16, 72);
                wmma::load_matrix_sync(bV[j], EVs + (kk * 16) * 72 + wn * 32 + j * 16, 72);
            }
#pragma unroll
            for (int i = 0; i < 2; i++)
#pragma unroll
                for (int j = 0; j < 2; j++) {
                    wmma::mma_sync(cN[i][j], a[i], bV[j], cN[i][j]);
                    wmma::mma_sync(cD[i][j], a[i], bK[j], cD[i][j]);
                }
        }
    }

    // Epilogue: stage num/den in smem, apply sigmoid(Q+bq)*num/den -> half Yt
    __syncthreads();
    float* num = (float*)sh;           // [64][68]
    float* den = num + 64 * 68;        // [64][68]
#pragma unroll
    for (int i = 0; i < 2; i++)
#pragma unroll
        for (int j = 0; j < 2; j++) {
            wmma::store_matrix_sync(&num[(wm * 32 + i * 16) * 68 + wn * 32 + j * 16],
                                    cN[i][j], 68, wmma::mem_row_major);
            wmma::store_matrix_sync(&den[(wm * 32 + i * 16) * 68 + wn * 32 + j * 16],
                                    cD[i][j], 68, wmma::mem_row_major);
        }
    __syncthreads();

#pragma unroll
    for (int it = 0; it < 8; it++) {
        const int f = tid + it * 128;        // 0..1023 f4 over 64x64
        const int row = f >> 4, c4 = f & 15;
        const size_t qidx = ((size_t)b * TT + t0 + row) * DD + d0 + c4 * 4;
        float4 q = *(const float4*)(Q + qidx);
        float4 b4 = __ldg((const float4*)(bq + d0 + c4 * 4));
        const float* np = &num[row * 68 + c4 * 4];
        const float* dp = &den[row * 68 + c4 * 4];
        float ox = (1.f / (1.f + expf(-(q.x + b4.x)))) * np[0] / dp[0];
        float oy = (1.f / (1.f + expf(-(q.y + b4.y)))) * np[1] / dp[1];
        float oz = (1.f / (1.f + expf(-(q.z + b4.z)))) * np[2] / dp[2];
        float ow = (1.f / (1.f + expf(-(q.w + b4.w)))) * np[3] / dp[3];
        __half2* yp = (__half2*)(Yt + qidx);
        yp[0] = __floats2half2_rn(ox, oy);
        yp[1] = __floats2half2_rn(oz, ow);
    }
}

// ===========================================================================
// Elementwise / conversion kernels
// ===========================================================================
__global__ __launch_bounds__(256)
void expw_kernel(const float* __restrict__ w, __half* __restrict__ ew)
{
    const int t = blockIdx.x;
    const float* row = w + (size_t)t * TT;
    float m = -INFINITY;
    for (int i = threadIdx.x; i < TT; i += 256) m = fmaxf(m, row[i]);
#pragma unroll
    for (int o = 16; o > 0; o >>= 1) m = fmaxf(m, __shfl_xor_sync(0xffffffffu, m, o));
    __shared__ float warpmax[8];
    __shared__ float rowmax;
    if ((threadIdx.x & 31) == 0) warpmax[threadIdx.x >> 5] = m;
    __syncthreads();
    if (threadIdx.x == 0) {
        float mm = warpmax[0];
#pragma unroll
        for (int i = 1; i < 8; i++) mm = fmaxf(mm, warpmax[i]);
        rowmax = mm;
    }
    __syncthreads();
    const float rm = rowmax;
    for (int i = threadIdx.x; i < TT; i += 256)
        ew[(size_t)t * TT + i] = __float2half(expf(row[i] - rm));
}

__global__ __launch_bounds__(256)
void kmax_kernel(const float* __restrict__ K, float* __restrict__ Kmax)
{
    const int idx = blockIdx.x * 256 + threadIdx.x;
    float m = -INFINITY;
#pragma unroll 4
    for (int b = 0; b < BB; b++)
        m = fmaxf(m, K[(size_t)b * TT * DD + idx]);
    Kmax[idx] = m;
}

__global__ __launch_bounds__(256)
void ekv_kernel(const float* __restrict__ K, const float* __restrict__ V,
                const float* __restrict__ Kmax, const float* __restrict__ bv,
                __half* __restrict__ EK, __half* __restrict__ EKV)
{
    const size_t idx = (size_t)blockIdx.x * 256 + threadIdx.x;
    const float ek = expf(K[idx] - Kmax[idx & (size_t)(TT * DD - 1)]);
    EK[idx]  = __float2half(ek);
    EKV[idx] = __float2half(ek * (V[idx] + bv[idx & (DD - 1)]));
}

__global__ void brep_fill(const float* __restrict__ bo, float* __restrict__ brep)
{
    const int idx = blockIdx.x * 256 + threadIdx.x;
    brep[idx] = bo[idx & (DD - 1)];
}

__global__ __launch_bounds__(256)
void f2h_kernel(const float* __restrict__ src, __half* __restrict__ dst)
{
    const size_t f = (size_t)blockIdx.x * 256 + threadIdx.x;   // f4 index
    float4 v = ((const float4*)src)[f];
    __half2* d = (__half2*)(dst + f * 4);
    d[0] = __floats2half2_rn(v.x, v.y);
    d[1] = __floats2half2_rn(v.z, v.w);
}

__global__ __launch_bounds__(256)
void wconv_kernel(const float* __restrict__ Wk, const float* __restrict__ Wv,
                  const float* __restrict__ Wq, const float* __restrict__ Wo,
                  __half* __restrict__ W3h, __half* __restrict__ Woh)
{
    const int f = blockIdx.x * 256 + threadIdx.x;    // f4 index < 4*65536
    const int per = DD * DD / 4;
    const float* src; __half* dst; int off;
    if (f < per)           { src = Wk; dst = W3h;            off = f; }
    else if (f < 2 * per)  { src = Wv; dst = W3h + DD * DD;  off = f - per; }
    else if (f < 3 * per)  { src = Wq; dst = W3h + 2*DD*DD;  off = f - 2 * per; }
    else                   { src = Wo; dst = Woh;            off = f - 3 * per; }
    float4 v = ((const float4*)src)[off];
    __half2* d = (__half2*)(dst + (size_t)off * 4);
    d[0] = __floats2half2_rn(v.x, v.y);
    d[1] = __floats2half2_rn(v.z, v.w);
}

// ===========================================================================
extern "C" void kernel_launch(void* const* d_in, const int* in_sizes, int n_in,
                              void* d_out, int out_size)
{
    const float* x    = (const float*)d_in[0];
    const float* Wk_w = (const float*)d_in[1];
    // Wk_b unused: K bias cancels inside exp(K - max_b K)
    const float* Wv_w = (const float*)d_in[3];
    const float* Wv_b = (const float*)d_in[4];
    const float* Wq_w = (const float*)d_in[5];
    const float* Wq_b = (const float*)d_in[6];
    const float* w    = (const float*)d_in[7];
    const float* Wo_w = (const float*)d_in[8];
    const float* Wo_b = (const float*)d_in[9];
    float* out = (float*)d_out;

    float *pK, *pV, *pQ, *pKmax, *pbrep;
    __half *pxh, *pW3h, *pWoh, *pexpwh, *pEKh, *pEKVh, *pYth;
    cudaGetSymbolAddress((void**)&pK, g_K);
    cudaGetSymbolAddress((void**)&pV, g_V);
    cudaGetSymbolAddress((void**)&pQ, g_Q);
    cudaGetSymbolAddress((void**)&pKmax, g_Kmax);
    cudaGetSymbolAddress((void**)&pbrep, g_brep);
    cudaGetSymbolAddress((void**)&pxh, g_xh);
    cudaGetSymbolAddress((void**)&pW3h, g_W3h);
    cudaGetSymbolAddress((void**)&pWoh, g_Woh);
    cudaGetSymbolAddress((void**)&pexpwh, g_expwh);
    cudaGetSymbolAddress((void**)&pEKh, g_EKh);
    cudaGetSymbolAddress((void**)&pEKVh, g_EKVh);
    cudaGetSymbolAddress((void**)&pYth, g_Yth);

    cudaFuncSetAttribute(linh,  cudaFuncAttributeMaxDynamicSharedMemorySize, L_SMEM);
    cudaFuncSetAttribute(attnh, cudaFuncAttributeMaxDynamicSharedMemorySize, A_SMEM);

    // Prep / conversions
    expw_kernel<<<TT, 256>>>(w, pexpwh);
    f2h_kernel<<<(MM * DD / 4) / 256, 256>>>(x, pxh);
    wconv_kernel<<<(4 * DD * DD / 4) / 256, 256>>>(Wk_w, Wv_w, Wq_w, Wo_w, pW3h, pWoh);
    brep_fill<<<(16 * DD) / 256, 256>>>(Wo_b, pbrep);

    // Fused K/V/Q linear: N = 1536 -> grid (12, 256)
    linh<<<dim3(12, MM / 128), 128, L_SMEM>>>(pxh, pW3h, pbrep, pK, pV, pQ, nullptr);

    kmax_kernel<<<(TT * DD) / 256, 256>>>(pK, pKmax);
    ekv_kernel<<<(BB * TT * DD) / 256, 256>>>(pK, pV, pKmax, Wv_b, pEKh, pEKVh);

    attnh<<<dim3(DD / 64, TT / 64, BB), 128, A_SMEM>>>(pexpwh, pEKh, pEKVh, pQ, Wq_b, pYth);

    // Final linear with bias: N = 512 -> grid (4, 256)
    linh<<<dim3(4, MM / 128), 128, L_SMEM>>>(pYth, pWoh, pbrep, nullptr, nullptr, nullptr, out);
}

// round 8
// speedup vs baseline: 5.5300x; 1.3424x over previous
#include <cuda_runtime.h>
#include <cuda_fp16.h>
#include <math.h>
#include <mma.h>
#include <stdint.h>

using namespace nvcuda;

#define BB 32
#define TT 1024
#define DD 512
#define MM (BB * TT)

// Scratch (__device__ globals; no allocations allowed)
__device__ float  g_K[MM * DD];
__device__ float  g_V[MM * DD];
__device__ float  g_Q[MM * DD];
__device__ float  g_brep[16 * DD];
__device__ __half g_xh[MM * DD];
__device__ __half g_W3h[3 * DD * DD];
__device__ __half g_Woh[DD * DD];
__device__ __half g_expwh[TT * TT];
__device__ __half g_EKh[MM * DD];
__device__ __half g_EKVh[MM * DD];
__device__ __half g_Yth[MM * DD];

__device__ __forceinline__ uint32_t smem_u32(const void* p) {
    uint32_t a;
    asm("{ .reg .u64 t; cvta.to.shared.u64 t, %1; cvt.u32.u64 %0, t; }"
        : "=r"(a) : "l"(p));
    return a;
}

#define CP16(dst, src) \
    asm volatile("cp.async.cg.shared.global [%0], [%1], 16;" \
        :: "r"(smem_u32(dst)), "l"((const void*)(src)) : "memory")
#define CP_COMMIT() asm volatile("cp.async.commit_group;" ::: "memory")
#define CP_WAIT0()  asm volatile("cp.async.wait_group 0;" ::: "memory")
#define CP_WAIT1()  asm volatile("cp.async.wait_group 1;" ::: "memory")
#define CP_WAIT2()  asm volatile("cp.async.wait_group 2;" ::: "memory")

// ===========================================================================
// Linear NT GEMM (fp16 WMMA, fp32 acc, 4-stage cp.async, 3 in flight)
// Block 128x128, 128 threads, 4 warps (2x2), warp tile 64x64. K-chunk 32.
// Fused mode (out==null): route output block to K/V/Q by n>>9.
// ===========================================================================
#define L_STAGE 10240   // halves per stage: As 128*40 + Bs 128*40
#define L_NST 4
#define L_SMEM (L_NST * L_STAGE * 2)   // 81920 B

__global__ __launch_bounds__(128)
void linh(const __half* __restrict__ A, const __half* __restrict__ W,
          const float* __restrict__ brep,
          float* __restrict__ K, float* __restrict__ V, float* __restrict__ Q,
          float* __restrict__ out)
{
    extern __shared__ __half sh[];
    const int tid = threadIdx.x;
    const int wid = tid >> 5;
    const int wm = wid >> 1;          // 0..1 (64 rows)
    const int wn = wid & 1;           // 0..1 (64 cols)
    const int m0 = blockIdx.y * 128, n0 = blockIdx.x * 128;

    wmma::fragment<wmma::accumulator, 16, 16, 16, float> c[4][4];
#pragma unroll
    for (int i = 0; i < 4; i++)
#pragma unroll
        for (int j = 0; j < 4; j++) {
            if (out)
                wmma::load_matrix_sync(c[i][j],
                    brep + ((n0 + wn * 64 + j * 16) & (DD - 1)),
                    DD, wmma::mem_row_major);
            else
                wmma::fill_fragment(c[i][j], 0.0f);
        }

    auto issue = [&](int chunk) {
        __half* As = sh + (chunk & (L_NST - 1)) * L_STAGE;
        __half* Bs = As + 128 * 40;
        const int k0 = chunk * 32;
#pragma unroll
        for (int i = 0; i < 4; i++) {
            const int f = tid + i * 128;
            const int row = f >> 2, c8 = f & 3;
            CP16(As + row * 40 + c8 * 8, A + (size_t)(m0 + row) * DD + k0 + c8 * 8);
        }
#pragma unroll
        for (int i = 0; i < 4; i++) {
            const int f = tid + i * 128;
            const int row = f >> 2, c8 = f & 3;
            CP16(Bs + row * 40 + c8 * 8, W + (size_t)(n0 + row) * DD + k0 + c8 * 8);
        }
        CP_COMMIT();
    };

    issue(0); issue(1); issue(2);

    const int NC = DD / 32;   // 16
    for (int ch = 0; ch < NC; ch++) {
        if (ch <= NC - 3)      CP_WAIT2();
        else if (ch == NC - 2) CP_WAIT1();
        else                   CP_WAIT0();
        __syncthreads();
        if (ch + 3 < NC) issue(ch + 3);

        const __half* As = sh + (ch & (L_NST - 1)) * L_STAGE;
        const __half* Bs = As + 128 * 40;
#pragma unroll
        for (int kk = 0; kk < 2; kk++) {
            wmma::fragment<wmma::matrix_a, 16, 16, 16, __half, wmma::row_major> a[4];
            wmma::fragment<wmma::matrix_b, 16, 16, 16, __half, wmma::col_major> b[4];
#pragma unroll
            for (int i = 0; i < 4; i++)
                wmma::load_matrix_sync(a[i], As + (wm * 64 + i * 16) * 40 + kk * 16, 40);
#pragma unroll
            for (int j = 0; j < 4; j++)
                wmma::load_matrix_sync(b[j], Bs + (wn * 64 + j * 16) * 40 + kk * 16, 40);
#pragma unroll
            for (int i = 0; i < 4; i++)
#pragma unroll
                for (int j = 0; j < 4; j++)
                    wmma::mma_sync(c[i][j], a[i], b[j], c[i][j]);
        }
    }

    float* dst;
    int col0;
    if (out) { dst = out; col0 = n0; }
    else {
        const int mat = n0 >> 9;
        dst = (mat == 0) ? K : (mat == 1) ? V : Q;
        col0 = n0 & 511;
    }
#pragma unroll
    for (int i = 0; i < 4; i++)
#pragma unroll
        for (int j = 0; j < 4; j++)
            wmma::store_matrix_sync(dst + (size_t)(m0 + wm * 64 + i * 16) * DD
                                        + col0 + wn * 64 + j * 16,
                                    c[i][j], DD, wmma::mem_row_major);
}

// ===========================================================================
// Attention (fp16 WMMA): num = expw @ EKV, den = expw @ EK per batch,
// epilogue Yt_h <- half( sigmoid(Q + bq) * num / den ).
// Block 128(t) x 64(d), 128 threads, 4 warps (2x2), warp tile 64t x 32d
// dual-acc (A fragments shared by num and den: 8 LDSM per 16 MMA).
// 4-stage cp.async pipeline, K(s)-chunk 32.
// ===========================================================================
#define A_STAGE 9728    // halves: Ws 128*40 + EK 32*72 + EKV 32*72
#define A_NST 4
#define A_SMEM (A_NST * A_STAGE * 2)   // 77824 B (epi needs 2*128*68*4 = 69632)

__global__ __launch_bounds__(128)
void attnh(const __half* __restrict__ expw, const __half* __restrict__ EK,
           const __half* __restrict__ EKV, const float* __restrict__ Q,
           const float* __restrict__ bq, __half* __restrict__ Yt)
{
    extern __shared__ __half sh[];
    const int tid = threadIdx.x;
    const int wid = tid >> 5;
    const int wm = wid >> 1;          // 0..1 (64 t-rows)
    const int wn = wid & 1;           // 0..1 (32 d-cols)
    const int d0 = blockIdx.x * 64, t0 = blockIdx.y * 128, b = blockIdx.z;

    const __half* ekb  = EK  + (size_t)b * TT * DD;
    const __half* ekvb = EKV + (size_t)b * TT * DD;

    wmma::fragment<wmma::accumulator, 16, 16, 16, float> cN[4][2], cD[4][2];
#pragma unroll
    for (int i = 0; i < 4; i++)
#pragma unroll
        for (int j = 0; j < 2; j++) {
            wmma::fill_fragment(cN[i][j], 0.0f);
            wmma::fill_fragment(cD[i][j], 0.0f);
        }

    auto issue = [&](int chunk) {
        __half* Ws  = sh + (chunk & (A_NST - 1)) * A_STAGE;
        __half* EKs = Ws + 128 * 40;
        __half* EVs = EKs + 32 * 72;
        const int s0 = chunk * 32;
#pragma unroll
        for (int i = 0; i < 4; i++) {          // Ws: 128x32 -> 512 cp16
            const int f = tid + i * 128;
            const int row = f >> 2, c8 = f & 3;
            CP16(Ws + row * 40 + c8 * 8, expw + (size_t)(t0 + row) * TT + s0 + c8 * 8);
        }
#pragma unroll
        for (int i = 0; i < 2; i++) {          // EK/EKV: 32x64 -> 256 cp16 each
            const int f = tid + i * 128;
            const int row = f >> 3, c8 = f & 7;
            CP16(EKs + row * 72 + c8 * 8, ekb  + (size_t)(s0 + row) * DD + d0 + c8 * 8);
            CP16(EVs + row * 72 + c8 * 8, ekvb + (size_t)(s0 + row) * DD + d0 + c8 * 8);
        }
        CP_COMMIT();
    };

    issue(0); issue(1); issue(2);

    const int NC = TT / 32;   // 32
    for (int ch = 0; ch < NC; ch++) {
        if (ch <= NC - 3)      CP_WAIT2();
        else if (ch == NC - 2) CP_WAIT1();
        else                   CP_WAIT0();
        __syncthreads();
        if (ch + 3 < NC) issue(ch + 3);

        const __half* Ws  = sh + (ch & (A_NST - 1)) * A_STAGE;
        const __half* EKs = Ws + 128 * 40;
        const __half* EVs = EKs + 32 * 72;
#pragma unroll
        for (int kk = 0; kk < 2; kk++) {
            wmma::fragment<wmma::matrix_a, 16, 16, 16, __half, wmma::row_major> a[4];
            wmma::fragment<wmma::matrix_b, 16, 16, 16, __half, wmma::row_major> bK[2], bV[2];
#pragma unroll
            for (int i = 0; i < 4; i++)
                wmma::load_matrix_sync(a[i], Ws + (wm * 64 + i * 16) * 40 + kk * 16, 40);
#pragma unroll
            for (int j = 0; j < 2; j++) {
                wmma::load_matrix_sync(bK[j], EKs + (kk * 16) * 72 + wn * 32 + j * 16, 72);
                wmma::load_matrix_sync(bV[j], EVs + (kk * 16) * 72 + wn * 32 + j * 16, 72);
            }
#pragma unroll
            for (int i = 0; i < 4; i++)
#pragma unroll
                for (int j = 0; j < 2; j++) {
                    wmma::mma_sync(cN[i][j], a[i], bV[j], cN[i][j]);
                    wmma::mma_sync(cD[i][j], a[i], bK[j], cD[i][j]);
                }
        }
    }

    // Epilogue: stage num/den in smem, apply sigmoid(Q+bq)*num/den -> half Yt
    __syncthreads();
    float* num = (float*)sh;           // [128][68]
    float* den = num + 128 * 68;       // [128][68]
#pragma unroll
    for (int i = 0; i < 4; i++)
#pragma unroll
        for (int j = 0; j < 2; j++) {
            wmma::store_matrix_sync(&num[(wm * 64 + i * 16) * 68 + wn * 32 + j * 16],
                                    cN[i][j], 68, wmma::mem_row_major);
            wmma::store_matrix_sync(&den[(wm * 64 + i * 16) * 68 + wn * 32 + j * 16],
                                    cD[i][j], 68, wmma::mem_row_major);
        }
    __syncthreads();

#pragma unroll
    for (int it = 0; it < 16; it++) {
        const int f = tid + it * 128;        // 0..2047 f4 over 128x64
        const int row = f >> 4, c4 = f & 15;
        const size_t qidx = ((size_t)b * TT + t0 + row) * DD + d0 + c4 * 4;
        float4 q = *(const float4*)(Q + qidx);
        float4 b4 = __ldg((const float4*)(bq + d0 + c4 * 4));
        const float* np = &num[row * 68 + c4 * 4];
        const float* dp = &den[row * 68 + c4 * 4];
        float ox = (1.f / (1.f + expf(-(q.x + b4.x)))) * np[0] / dp[0];
        float oy = (1.f / (1.f + expf(-(q.y + b4.y)))) * np[1] / dp[1];
        float oz = (1.f / (1.f + expf(-(q.z + b4.z)))) * np[2] / dp[2];
        float ow = (1.f / (1.f + expf(-(q.w + b4.w)))) * np[3] / dp[3];
        __half2* yp = (__half2*)(Yt + qidx);
        yp[0] = __floats2half2_rn(ox, oy);
        yp[1] = __floats2half2_rn(oz, ow);
    }
}

// ===========================================================================
// Elementwise / conversion kernels
// ===========================================================================
__global__ __launch_bounds__(256)
void expw_kernel(const float* __restrict__ w, __half* __restrict__ ew)
{
    const int t = blockIdx.x;
    const float* row = w + (size_t)t * TT;
    float m = -INFINITY;
    for (int i = threadIdx.x; i < TT; i += 256) m = fmaxf(m, row[i]);
#pragma unroll
    for (int o = 16; o > 0; o >>= 1) m = fmaxf(m, __shfl_xor_sync(0xffffffffu, m, o));
    __shared__ float warpmax[8];
    __shared__ float rowmax;
    if ((threadIdx.x & 31) == 0) warpmax[threadIdx.x >> 5] = m;
    __syncthreads();
    if (threadIdx.x == 0) {
        float mm = warpmax[0];
#pragma unroll
        for (int i = 1; i < 8; i++) mm = fmaxf(mm, warpmax[i]);
        rowmax = mm;
    }
    __syncthreads();
    const float rm = rowmax;
    for (int i = threadIdx.x; i < TT; i += 256)
        ew[(size_t)t * TT + i] = __float2half(expf(row[i] - rm));
}

// Fused batch-max + exp + bias-fold: single pass over K (batch column kept
// in registers), then EK = exp(K - max_b K), EKV = EK * (V + bv).
__global__ __launch_bounds__(256)
void kmax_ekv_kernel(const float* __restrict__ K, const float* __restrict__ V,
                     const float* __restrict__ bv,
                     __half* __restrict__ EK, __half* __restrict__ EKV)
{
    const int idx = blockIdx.x * 256 + threadIdx.x;   // < TT*DD
    const float bvd = bv[idx & (DD - 1)];
    float kv[BB];
    float m = -INFINITY;
#pragma unroll
    for (int b = 0; b < BB; b++) {
        kv[b] = K[(size_t)b * TT * DD + idx];
        m = fmaxf(m, kv[b]);
    }
#pragma unroll
    for (int b = 0; b < BB; b++) {
        const size_t gi = (size_t)b * TT * DD + idx;
        const float ek = expf(kv[b] - m);
        EK[gi]  = __float2half(ek);
        EKV[gi] = __float2half(ek * (V[gi] + bvd));
    }
}

__global__ void brep_fill(const float* __restrict__ bo, float* __restrict__ brep)
{
    const int idx = blockIdx.x * 256 + threadIdx.x;
    brep[idx] = bo[idx & (DD - 1)];
}

__global__ __launch_bounds__(256)
void f2h_kernel(const float* __restrict__ src, __half* __restrict__ dst)
{
    const size_t f = (size_t)blockIdx.x * 256 + threadIdx.x;   // f4 index
    float4 v = ((const float4*)src)[f];
    __half2* d = (__half2*)(dst + f * 4);
    d[0] = __floats2half2_rn(v.x, v.y);
    d[1] = __floats2half2_rn(v.z, v.w);
}

__global__ __launch_bounds__(256)
void wconv_kernel(const float* __restrict__ Wk, const float* __restrict__ Wv,
                  const float* __restrict__ Wq, const float* __restrict__ Wo,
                  __half* __restrict__ W3h, __half* __restrict__ Woh)
{
    const int f = blockIdx.x * 256 + threadIdx.x;    // f4 index < 4*65536
    const int per = DD * DD / 4;
    const float* src; __half* dst; int off;
    if (f < per)           { src = Wk; dst = W3h;            off = f; }
    else if (f < 2 * per)  { src = Wv; dst = W3h + DD * DD;  off = f - per; }
    else if (f < 3 * per)  { src = Wq; dst = W3h + 2*DD*DD;  off = f - 2 * per; }
    else                   { src = Wo; dst = Woh;            off = f - 3 * per; }
    float4 v = ((const float4*)src)[off];
    __half2* d = (__half2*)(dst + (size_t)off * 4);
    d[0] = __floats2half2_rn(v.x, v.y);
    d[1] = __floats2half2_rn(v.z, v.w);
}

// ===========================================================================
extern "C" void kernel_launch(void* const* d_in, const int* in_sizes, int n_in,
                              void* d_out, int out_size)
{
    const float* x    = (const float*)d_in[0];
    const float* Wk_w = (const float*)d_in[1];
    // Wk_b unused: K bias cancels inside exp(K - max_b K)
    const float* Wv_w = (const float*)d_in[3];
    const float* Wv_b = (const float*)d_in[4];
    const float* Wq_w = (const float*)d_in[5];
    const float* Wq_b = (const float*)d_in[6];
    const float* w    = (const float*)d_in[7];
    const float* Wo_w = (const float*)d_in[8];
    const float* Wo_b = (const float*)d_in[9];
    float* out = (float*)d_out;

    float *pK, *pV, *pQ, *pbrep;
    __half *pxh, *pW3h, *pWoh, *pexpwh, *pEKh, *pEKVh, *pYth;
    cudaGetSymbolAddress((void**)&pK, g_K);
    cudaGetSymbolAddress((void**)&pV, g_V);
    cudaGetSymbolAddress((void**)&pQ, g_Q);
    cudaGetSymbolAddress((void**)&pbrep, g_brep);
    cudaGetSymbolAddress((void**)&pxh, g_xh);
    cudaGetSymbolAddress((void**)&pW3h, g_W3h);
    cudaGetSymbolAddress((void**)&pWoh, g_Woh);
    cudaGetSymbolAddress((void**)&pexpwh, g_expwh);
    cudaGetSymbolAddress((void**)&pEKh, g_EKh);
    cudaGetSymbolAddress((void**)&pEKVh, g_EKVh);
    cudaGetSymbolAddress((void**)&pYth, g_Yth);

    cudaFuncSetAttribute(linh,  cudaFuncAttributeMaxDynamicSharedMemorySize, L_SMEM);
    cudaFuncSetAttribute(attnh, cudaFuncAttributeMaxDynamicSharedMemorySize, A_SMEM);

    // Prep / conversions
    expw_kernel<<<TT, 256>>>(w, pexpwh);
    f2h_kernel<<<(MM * DD / 4) / 256, 256>>>(x, pxh);
    wconv_kernel<<<(4 * DD * DD / 4) / 256, 256>>>(Wk_w, Wv_w, Wq_w, Wo_w, pW3h, pWoh);
    brep_fill<<<(16 * DD) / 256, 256>>>(Wo_b, pbrep);

    // Fused K/V/Q linear: N = 1536 -> grid (12, 256)
    linh<<<dim3(12, MM / 128), 128, L_SMEM>>>(pxh, pW3h, pbrep, pK, pV, pQ, nullptr);

    // Fused batch-max + exp (+ V bias)
    kmax_ekv_kernel<<<(TT * DD) / 256, 256>>>(pK, pV, Wv_b, pEKh, pEKVh);

    attnh<<<dim3(DD / 64, TT / 128, BB), 128, A_SMEM>>>(pexpwh, pEKh, pEKVh, pQ, Wq_b, pYth);

    // Final linear with bias: N = 512 -> grid (4, 256)
    linh<<<dim3(4, MM / 128), 128, L_SMEM>>>(pYth, pWoh, pbrep, nullptr, nullptr, nullptr, out);
}

// round 9
// speedup vs baseline: 5.6161x; 1.0156x over previous
#include <cuda_runtime.h>
#include <cuda_fp16.h>
#include <math.h>
#include <mma.h>
#include <stdint.h>

using namespace nvcuda;

#define BB 32
#define TT 1024
#define DD 512
#define MM (BB * TT)

// Scratch (__device__ globals; no allocations allowed)
__device__ float  g_brep[16 * DD];
__device__ __half g_Kh[MM * DD];
__device__ __half g_Vh[MM * DD];
__device__ __half g_Qh[MM * DD];
__device__ __half g_xh[MM * DD];
__device__ __half g_W3h[3 * DD * DD];
__device__ __half g_Woh[DD * DD];
__device__ __half g_expwh[TT * TT];
__device__ __half g_EKh[MM * DD];
__device__ __half g_EKVh[MM * DD];
__device__ __half g_Yth[MM * DD];

__device__ __forceinline__ uint32_t smem_u32(const void* p) {
    uint32_t a;
    asm("{ .reg .u64 t; cvta.to.shared.u64 t, %1; cvt.u32.u64 %0, t; }"
        : "=r"(a) : "l"(p));
    return a;
}

#define CP16(dst, src) \
    asm volatile("cp.async.cg.shared.global [%0], [%1], 16;" \
        :: "r"(smem_u32(dst)), "l"((const void*)(src)) : "memory")
#define CP_COMMIT() asm volatile("cp.async.commit_group;" ::: "memory")
#define CP_WAIT0()  asm volatile("cp.async.wait_group 0;" ::: "memory")
#define CP_WAIT1()  asm volatile("cp.async.wait_group 1;" ::: "memory")
#define CP_WAIT2()  asm volatile("cp.async.wait_group 2;" ::: "memory")

// ===========================================================================
// Linear NT GEMM (fp16 WMMA, fp32 acc, 4-stage cp.async, 3 in flight)
// Block 128x128, 128 threads, 4 warps (2x2), warp tile 64x64. K-chunk 32.
// Fused mode (outf==null): convert acc to half, route to Kh/Vh/Qh by n>>9.
// Final mode (outf!=null): fp32 out with bias (acc init from brep).
// ===========================================================================
#define L_STAGE 10240   // halves per stage: As 128*40 + Bs 128*40
#define L_NST 4
#define L_SMEM (L_NST * L_STAGE * 2)   // 81920 B

__global__ __launch_bounds__(128)
void linh(const __half* __restrict__ A, const __half* __restrict__ W,
          const float* __restrict__ brep,
          __half* __restrict__ Kh, __half* __restrict__ Vh, __half* __restrict__ Qh,
          float* __restrict__ outf)
{
    extern __shared__ __half sh[];
    const int tid = threadIdx.x;
    const int wid = tid >> 5;
    const int wm = wid >> 1;          // 0..1 (64 rows)
    const int wn = wid & 1;           // 0..1 (64 cols)
    const int m0 = blockIdx.y * 128, n0 = blockIdx.x * 128;

    wmma::fragment<wmma::accumulator, 16, 16, 16, float> c[4][4];
#pragma unroll
    for (int i = 0; i < 4; i++)
#pragma unroll
        for (int j = 0; j < 4; j++) {
            if (outf)
                wmma::load_matrix_sync(c[i][j],
                    brep + ((n0 + wn * 64 + j * 16) & (DD - 1)),
                    DD, wmma::mem_row_major);
            else
                wmma::fill_fragment(c[i][j], 0.0f);
        }

    auto issue = [&](int chunk) {
        __half* As = sh + (chunk & (L_NST - 1)) * L_STAGE;
        __half* Bs = As + 128 * 40;
        const int k0 = chunk * 32;
#pragma unroll
        for (int i = 0; i < 4; i++) {
            const int f = tid + i * 128;
            const int row = f >> 2, c8 = f & 3;
            CP16(As + row * 40 + c8 * 8, A + (size_t)(m0 + row) * DD + k0 + c8 * 8);
        }
#pragma unroll
        for (int i = 0; i < 4; i++) {
            const int f = tid + i * 128;
            const int row = f >> 2, c8 = f & 3;
            CP16(Bs + row * 40 + c8 * 8, W + (size_t)(n0 + row) * DD + k0 + c8 * 8);
        }
        CP_COMMIT();
    };

    issue(0); issue(1); issue(2);

    const int NC = DD / 32;   // 16
    for (int ch = 0; ch < NC; ch++) {
        if (ch <= NC - 3)      CP_WAIT2();
        else if (ch == NC - 2) CP_WAIT1();
        else                   CP_WAIT0();
        __syncthreads();
        if (ch + 3 < NC) issue(ch + 3);

        const __half* As = sh + (ch & (L_NST - 1)) * L_STAGE;
        const __half* Bs = As + 128 * 40;
#pragma unroll
        for (int kk = 0; kk < 2; kk++) {
            wmma::fragment<wmma::matrix_a, 16, 16, 16, __half, wmma::row_major> a[4];
            wmma::fragment<wmma::matrix_b, 16, 16, 16, __half, wmma::col_major> b[4];
#pragma unroll
            for (int i = 0; i < 4; i++)
                wmma::load_matrix_sync(a[i], As + (wm * 64 + i * 16) * 40 + kk * 16, 40);
#pragma unroll
            for (int j = 0; j < 4; j++)
                wmma::load_matrix_sync(b[j], Bs + (wn * 64 + j * 16) * 40 + kk * 16, 40);
#pragma unroll
            for (int i = 0; i < 4; i++)
#pragma unroll
                for (int j = 0; j < 4; j++)
                    wmma::mma_sync(c[i][j], a[i], b[j], c[i][j]);
        }
    }

    if (outf) {
#pragma unroll
        for (int i = 0; i < 4; i++)
#pragma unroll
            for (int j = 0; j < 4; j++)
                wmma::store_matrix_sync(outf + (size_t)(m0 + wm * 64 + i * 16) * DD
                                             + n0 + wn * 64 + j * 16,
                                        c[i][j], DD, wmma::mem_row_major);
    } else {
        const int mat = n0 >> 9;
        __half* dst = (mat == 0) ? Kh : (mat == 1) ? Vh : Qh;
        const int col0 = n0 & 511;
        wmma::fragment<wmma::accumulator, 16, 16, 16, __half> chf;
#pragma unroll
        for (int i = 0; i < 4; i++)
#pragma unroll
            for (int j = 0; j < 4; j++) {
#pragma unroll
                for (int e = 0; e < chf.num_elements; e++)
                    chf.x[e] = __float2half(c[i][j].x[e]);
                wmma::store_matrix_sync(dst + (size_t)(m0 + wm * 64 + i * 16) * DD
                                            + col0 + wn * 64 + j * 16,
                                        chf, DD, wmma::mem_row_major);
            }
    }
}

// ===========================================================================
// Attention (fp16 WMMA): num = expw @ EKV, den = expw @ EK per batch.
// Division done in registers (cN/cD element-aligned); only the ratio is
// staged in smem. Epilogue: Yt_h <- half( sigmoid(Qh + bq) * ratio ).
// Block 128(t) x 64(d), 128 threads, 4 warps (2x2), warp 64x32 dual-acc.
// ===========================================================================
#define A_STAGE 9728    // halves: Ws 128*40 + EK 32*72 + EKV 32*72
#define A_NST 4
#define A_SMEM (A_NST * A_STAGE * 2)   // 77824 B (epi ratio: 128*68*4 = 34816)

__global__ __launch_bounds__(128)
void attnh(const __half* __restrict__ expw, const __half* __restrict__ EK,
           const __half* __restrict__ EKV, const __half* __restrict__ Qh,
           const float* __restrict__ bq, __half* __restrict__ Yt)
{
    extern __shared__ __half sh[];
    const int tid = threadIdx.x;
    const int wid = tid >> 5;
    const int wm = wid >> 1;          // 0..1 (64 t-rows)
    const int wn = wid & 1;           // 0..1 (32 d-cols)
    const int d0 = blockIdx.x * 64, t0 = blockIdx.y * 128, b = blockIdx.z;

    const __half* ekb  = EK  + (size_t)b * TT * DD;
    const __half* ekvb = EKV + (size_t)b * TT * DD;

    wmma::fragment<wmma::accumulator, 16, 16, 16, float> cN[4][2], cD[4][2];
#pragma unroll
    for (int i = 0; i < 4; i++)
#pragma unroll
        for (int j = 0; j < 2; j++) {
            wmma::fill_fragment(cN[i][j], 0.0f);
            wmma::fill_fragment(cD[i][j], 0.0f);
        }

    auto issue = [&](int chunk) {
        __half* Ws  = sh + (chunk & (A_NST - 1)) * A_STAGE;
        __half* EKs = Ws + 128 * 40;
        __half* EVs = EKs + 32 * 72;
        const int s0 = chunk * 32;
#pragma unroll
        for (int i = 0; i < 4; i++) {          // Ws: 128x32 -> 512 cp16
            const int f = tid + i * 128;
            const int row = f >> 2, c8 = f & 3;
            CP16(Ws + row * 40 + c8 * 8, expw + (size_t)(t0 + row) * TT + s0 + c8 * 8);
        }
#pragma unroll
        for (int i = 0; i < 2; i++) {          // EK/EKV: 32x64 -> 256 cp16 each
            const int f = tid + i * 128;
            const int row = f >> 3, c8 = f & 7;
            CP16(EKs + row * 72 + c8 * 8, ekb  + (size_t)(s0 + row) * DD + d0 + c8 * 8);
            CP16(EVs + row * 72 + c8 * 8, ekvb + (size_t)(s0 + row) * DD + d0 + c8 * 8);
        }
        CP_COMMIT();
    };

    issue(0); issue(1); issue(2);

    const int NC = TT / 32;   // 32
    for (int ch = 0; ch < NC; ch++) {
        if (ch <= NC - 3)      CP_WAIT2();
        else if (ch == NC - 2) CP_WAIT1();
        else                   CP_WAIT0();
        __syncthreads();
        if (ch + 3 < NC) issue(ch + 3);

        const __half* Ws  = sh + (ch & (A_NST - 1)) * A_STAGE;
        const __half* EKs = Ws + 128 * 40;
        const __half* EVs = EKs + 32 * 72;
#pragma unroll
        for (int kk = 0; kk < 2; kk++) {
            wmma::fragment<wmma::matrix_a, 16, 16, 16, __half, wmma::row_major> a[4];
            wmma::fragment<wmma::matrix_b, 16, 16, 16, __half, wmma::row_major> bK[2], bV[2];
#pragma unroll
            for (int i = 0; i < 4; i++)
                wmma::load_matrix_sync(a[i], Ws + (wm * 64 + i * 16) * 40 + kk * 16, 40);
#pragma unroll
            for (int j = 0; j < 2; j++) {
                wmma::load_matrix_sync(bK[j], EKs + (kk * 16) * 72 + wn * 32 + j * 16, 72);
                wmma::load_matrix_sync(bV[j], EVs + (kk * 16) * 72 + wn * 32 + j * 16, 72);
            }
#pragma unroll
            for (int i = 0; i < 4; i++)
#pragma unroll
                for (int j = 0; j < 2; j++) {
                    wmma::mma_sync(cN[i][j], a[i], bV[j], cN[i][j]);
                    wmma::mma_sync(cD[i][j], a[i], bK[j], cD[i][j]);
                }
        }
    }

    // Divide in registers (cN/cD are element-aligned), stage only the ratio
    __syncthreads();
    float* ratio = (float*)sh;           // [128][68]
#pragma unroll
    for (int i = 0; i < 4; i++)
#pragma unroll
        for (int j = 0; j < 2; j++) {
#pragma unroll
            for (int e = 0; e < cN[i][j].num_elements; e++)
                cN[i][j].x[e] /= cD[i][j].x[e];
            wmma::store_matrix_sync(&ratio[(wm * 64 + i * 16) * 68 + wn * 32 + j * 16],
                                    cN[i][j], 68, wmma::mem_row_major);
        }
    __syncthreads();

#pragma unroll
    for (int it = 0; it < 16; it++) {
        const int f = tid + it * 128;        // 0..2047 groups of 4 over 128x64
        const int row = f >> 4, c4 = f & 15;
        const size_t qidx = ((size_t)b * TT + t0 + row) * DD + d0 + c4 * 4;
        const __half2* qp = (const __half2*)(Qh + qidx);
        float2 q01 = __half22float2(qp[0]);
        float2 q23 = __half22float2(qp[1]);
        float4 b4 = __ldg((const float4*)(bq + d0 + c4 * 4));
        const float* rp = &ratio[row * 68 + c4 * 4];
        float ox = (1.f / (1.f + expf(-(q01.x + b4.x)))) * rp[0];
        float oy = (1.f / (1.f + expf(-(q01.y + b4.y)))) * rp[1];
        float oz = (1.f / (1.f + expf(-(q23.x + b4.z)))) * rp[2];
        float ow = (1.f / (1.f + expf(-(q23.y + b4.w)))) * rp[3];
        __half2* yp = (__half2*)(Yt + qidx);
        yp[0] = __floats2half2_rn(ox, oy);
        yp[1] = __floats2half2_rn(oz, ow);
    }
}

// ===========================================================================
// Elementwise / conversion kernels
// ===========================================================================
__global__ __launch_bounds__(256)
void expw_kernel(const float* __restrict__ w, __half* __restrict__ ew)
{
    const int t = blockIdx.x;
    const float* row = w + (size_t)t * TT;
    float m = -INFINITY;
    for (int i = threadIdx.x; i < TT; i += 256) m = fmaxf(m, row[i]);
#pragma unroll
    for (int o = 16; o > 0; o >>= 1) m = fmaxf(m, __shfl_xor_sync(0xffffffffu, m, o));
    __shared__ float warpmax[8];
    __shared__ float rowmax;
    if ((threadIdx.x & 31) == 0) warpmax[threadIdx.x >> 5] = m;
    __syncthreads();
    if (threadIdx.x == 0) {
        float mm = warpmax[0];
#pragma unroll
        for (int i = 1; i < 8; i++) mm = fmaxf(mm, warpmax[i]);
        rowmax = mm;
    }
    __syncthreads();
    const float rm = rowmax;
    for (int i = threadIdx.x; i < TT; i += 256)
        ew[(size_t)t * TT + i] = __float2half(expf(row[i] - rm));
}

// Fused batch-max + exp + bias-fold over half K/V (half2 lanes):
// EK = exp(K - max_b K), EKV = EK * (V + bv)
__global__ __launch_bounds__(256)
void kmax_ekv_kernel(const __half* __restrict__ Kh, const __half* __restrict__ Vh,
                     const float* __restrict__ bv,
                     __half* __restrict__ EK, __half* __restrict__ EKV)
{
    const int idx = (blockIdx.x * 256 + threadIdx.x) * 2;   // < TT*DD
    const float bv0 = bv[idx & (DD - 1)];
    const float bv1 = bv[(idx + 1) & (DD - 1)];
    float2 kv[BB];
    float m0 = -INFINITY, m1 = -INFINITY;
#pragma unroll
    for (int b = 0; b < BB; b++) {
        kv[b] = __half22float2(*(const __half2*)(Kh + (size_t)b * TT * DD + idx));
        m0 = fmaxf(m0, kv[b].x);
        m1 = fmaxf(m1, kv[b].y);
    }
#pragma unroll
    for (int b = 0; b < BB; b++) {
        const size_t gi = (size_t)b * TT * DD + idx;
        float2 v = __half22float2(*(const __half2*)(Vh + gi));
        const float e0 = expf(kv[b].x - m0);
        const float e1 = expf(kv[b].y - m1);
        *(__half2*)(EK + gi)  = __floats2half2_rn(e0, e1);
        *(__half2*)(EKV + gi) = __floats2half2_rn(e0 * (v.x + bv0), e1 * (v.y + bv1));
    }
}

__global__ void brep_fill(const float* __restrict__ bo, float* __restrict__ brep)
{
    const int idx = blockIdx.x * 256 + threadIdx.x;
    brep[idx] = bo[idx & (DD - 1)];
}

__global__ __launch_bounds__(256)
void f2h_kernel(const float* __restrict__ src, __half* __restrict__ dst)
{
    const size_t f = (size_t)blockIdx.x * 256 + threadIdx.x;   // f4 index
    float4 v = ((const float4*)src)[f];
    __half2* d = (__half2*)(dst + f * 4);
    d[0] = __floats2half2_rn(v.x, v.y);
    d[1] = __floats2half2_rn(v.z, v.w);
}

__global__ __launch_bounds__(256)
void wconv_kernel(const float* __restrict__ Wk, const float* __restrict__ Wv,
                  const float* __restrict__ Wq, const float* __restrict__ Wo,
                  __half* __restrict__ W3h, __half* __restrict__ Woh)
{
    const int f = blockIdx.x * 256 + threadIdx.x;    // f4 index < 4*65536
    const int per = DD * DD / 4;
    const float* src; __half* dst; int off;
    if (f < per)           { src = Wk; dst = W3h;            off = f; }
    else if (f < 2 * per)  { src = Wv; dst = W3h + DD * DD;  off = f - per; }
    else if (f < 3 * per)  { src = Wq; dst = W3h + 2*DD*DD;  off = f - 2 * per; }
    else                   { src = Wo; dst = Woh;            off = f - 3 * per; }
    float4 v = ((const float4*)src)[off];
    __half2* d = (__half2*)(dst + (size_t)off * 4);
    d[0] = __floats2half2_rn(v.x, v.y);
    d[1] = __floats2half2_rn(v.z, v.w);
}

// ===========================================================================
extern "C" void kernel_launch(void* const* d_in, const int* in_sizes, int n_in,
                              void* d_out, int out_size)
{
    const float* x    = (const float*)d_in[0];
    const float* Wk_w = (const float*)d_in[1];
    // Wk_b unused: K bias cancels inside exp(K - max_b K)
    const float* Wv_w = (const float*)d_in[3];
    const float* Wv_b = (const float*)d_in[4];
    const float* Wq_w = (const float*)d_in[5];
    const float* Wq_b = (const float*)d_in[6];
    const float* w    = (const float*)d_in[7];
    const float* Wo_w = (const float*)d_in[8];
    const float* Wo_b = (const float*)d_in[9];
    float* out = (float*)d_out;

    float *pbrep;
    __half *pKh, *pVh, *pQh, *pxh, *pW3h, *pWoh, *pexpwh, *pEKh, *pEKVh, *pYth;
    cudaGetSymbolAddress((void**)&pbrep, g_brep);
    cudaGetSymbolAddress((void**)&pKh, g_Kh);
    cudaGetSymbolAddress((void**)&pVh, g_Vh);
    cudaGetSymbolAddress((void**)&pQh, g_Qh);
    cudaGetSymbolAddress((void**)&pxh, g_xh);
    cudaGetSymbolAddress((void**)&pW3h, g_W3h);
    cudaGetSymbolAddress((void**)&pWoh, g_Woh);
    cudaGetSymbolAddress((void**)&pexpwh, g_expwh);
    cudaGetSymbolAddress((void**)&pEKh, g_EKh);
    cudaGetSymbolAddress((void**)&pEKVh, g_EKVh);
    cudaGetSymbolAddress((void**)&pYth, g_Yth);

    cudaFuncSetAttribute(linh,  cudaFuncAttributeMaxDynamicSharedMemorySize, L_SMEM);
    cudaFuncSetAttribute(attnh, cudaFuncAttributeMaxDynamicSharedMemorySize, A_SMEM);

    // Prep (ordered so launch #4 = fused KVQ GEMM, which ncu captures)
    f2h_kernel<<<(MM * DD / 4) / 256, 256>>>(x, pxh);
    wconv_kernel<<<(4 * DD * DD / 4) / 256, 256>>>(Wk_w, Wv_w, Wq_w, Wo_w, pW3h, pWoh);
    expw_kernel<<<TT, 256>>>(w, pexpwh);

    // #4: fused K/V/Q linear (half out): N = 1536 -> grid (12, 256)
    linh<<<dim3(12, MM / 128), 128, L_SMEM>>>(pxh, pW3h, pbrep, pKh, pVh, pQh, nullptr);

    brep_fill<<<(16 * DD) / 256, 256>>>(Wo_b, pbrep);
    kmax_ekv_kernel<<<(TT * DD / 2) / 256, 256>>>(pKh, pVh, Wv_b, pEKh, pEKVh);

    attnh<<<dim3(DD / 64, TT / 128, BB), 128, A_SMEM>>>(pexpwh, pEKh, pEKVh, pQh, Wq_b, pYth);

    // Final linear with bias (fp32 out): N = 512 -> grid (4, 256)
    linh<<<dim3(4, MM / 128), 128, L_SMEM>>>(pYth, pWoh, pbrep, nullptr, nullptr, nullptr, out);
}

// round 10
// speedup vs baseline: 6.4120x; 1.1417x over previous
#include <cuda_runtime.h>
#include <cuda_fp16.h>
#include <math.h>
#include <mma.h>
#include <stdint.h>

using namespace nvcuda;

#define BB 32
#define TT 1024
#define DD 512
#define MM (BB * TT)

// Scratch (__device__ globals; no allocations allowed)
__device__ float  g_brep[16 * DD];
__device__ __half g_Kh[MM * DD];
__device__ __half g_Vh[MM * DD];
__device__ __half g_Qh[MM * DD];
__device__ __half g_xh[MM * DD];
__device__ __half g_W3h[3 * DD * DD];
__device__ __half g_Woh[DD * DD];
__device__ __half g_expwh[TT * TT];
__device__ __half g_EKh[MM * DD];
__device__ __half g_EKVh[MM * DD];
__device__ __half g_Yth[MM * DD];

__device__ __forceinline__ uint32_t smem_u32(const void* p) {
    uint32_t a;
    asm("{ .reg .u64 t; cvta.to.shared.u64 t, %1; cvt.u32.u64 %0, t; }"
        : "=r"(a) : "l"(p));
    return a;
}

#define CP16(dst, src) \
    asm volatile("cp.async.cg.shared.global [%0], [%1], 16;" \
        :: "r"(smem_u32(dst)), "l"((const void*)(src)) : "memory")
#define CP_COMMIT() asm volatile("cp.async.commit_group;" ::: "memory")
#define CP_WAIT0()  asm volatile("cp.async.wait_group 0;" ::: "memory")
#define CP_WAIT1()  asm volatile("cp.async.wait_group 1;" ::: "memory")

// ===========================================================================
// Linear NT GEMM (fp16 WMMA, fp32 acc, 3-stage cp.async, 2 in flight)
// Block 128x128, 128 threads, 4 warps (2x2), warp tile 64x64. K-chunk 32.
// 3 CTAs/SM (smem 61440 B, regs capped by launch_bounds).
// Fused mode (outf==null): convert acc to half, route to Kh/Vh/Qh by n>>9.
// ===========================================================================
#define L_STAGE 10240   // halves per stage: As 128*40 + Bs 128*40
#define L_NST 3
#define L_SMEM (L_NST * L_STAGE * 2)   // 61440 B

__global__ __launch_bounds__(128, 3)
void linh(const __half* __restrict__ A, const __half* __restrict__ W,
          const float* __restrict__ brep,
          __half* __restrict__ Kh, __half* __restrict__ Vh, __half* __restrict__ Qh,
          float* __restrict__ outf)
{
    extern __shared__ __half sh[];
    const int tid = threadIdx.x;
    const int wid = tid >> 5;
    const int wm = wid >> 1;          // 0..1 (64 rows)
    const int wn = wid & 1;           // 0..1 (64 cols)
    const int m0 = blockIdx.y * 128, n0 = blockIdx.x * 128;

    wmma::fragment<wmma::accumulator, 16, 16, 16, float> c[4][4];
#pragma unroll
    for (int i = 0; i < 4; i++)
#pragma unroll
        for (int j = 0; j < 4; j++) {
            if (outf)
                wmma::load_matrix_sync(c[i][j],
                    brep + ((n0 + wn * 64 + j * 16) & (DD - 1)),
                    DD, wmma::mem_row_major);
            else
                wmma::fill_fragment(c[i][j], 0.0f);
        }

    auto issue = [&](int chunk) {
        __half* As = sh + (chunk % L_NST) * L_STAGE;
        __half* Bs = As + 128 * 40;
        const int k0 = chunk * 32;
#pragma unroll
        for (int i = 0; i < 4; i++) {
            const int f = tid + i * 128;
            const int row = f >> 2, c8 = f & 3;
            CP16(As + row * 40 + c8 * 8, A + (size_t)(m0 + row) * DD + k0 + c8 * 8);
        }
#pragma unroll
        for (int i = 0; i < 4; i++) {
            const int f = tid + i * 128;
            const int row = f >> 2, c8 = f & 3;
            CP16(Bs + row * 40 + c8 * 8, W + (size_t)(n0 + row) * DD + k0 + c8 * 8);
        }
        CP_COMMIT();
    };

    issue(0); issue(1);

    const int NC = DD / 32;   // 16
    for (int ch = 0; ch < NC; ch++) {
        if (ch <= NC - 2) CP_WAIT1();
        else              CP_WAIT0();
        __syncthreads();
        if (ch + 2 < NC) issue(ch + 2);

        const __half* As = sh + (ch % L_NST) * L_STAGE;
        const __half* Bs = As + 128 * 40;
#pragma unroll
        for (int kk = 0; kk < 2; kk++) {
            wmma::fragment<wmma::matrix_a, 16, 16, 16, __half, wmma::row_major> a[4];
            wmma::fragment<wmma::matrix_b, 16, 16, 16, __half, wmma::col_major> b[4];
#pragma unroll
            for (int i = 0; i < 4; i++)
                wmma::load_matrix_sync(a[i], As + (wm * 64 + i * 16) * 40 + kk * 16, 40);
#pragma unroll
            for (int j = 0; j < 4; j++)
                wmma::load_matrix_sync(b[j], Bs + (wn * 64 + j * 16) * 40 + kk * 16, 40);
#pragma unroll
            for (int i = 0; i < 4; i++)
#pragma unroll
                for (int j = 0; j < 4; j++)
                    wmma::mma_sync(c[i][j], a[i], b[j], c[i][j]);
        }
    }

    if (outf) {
#pragma unroll
        for (int i = 0; i < 4; i++)
#pragma unroll
            for (int j = 0; j < 4; j++)
                wmma::store_matrix_sync(outf + (size_t)(m0 + wm * 64 + i * 16) * DD
                                             + n0 + wn * 64 + j * 16,
                                        c[i][j], DD, wmma::mem_row_major);
    } else {
        const int mat = n0 >> 9;
        __half* dst = (mat == 0) ? Kh : (mat == 1) ? Vh : Qh;
        const int col0 = n0 & 511;
        wmma::fragment<wmma::accumulator, 16, 16, 16, __half> chf;
#pragma unroll
        for (int i = 0; i < 4; i++)
#pragma unroll
            for (int j = 0; j < 4; j++) {
#pragma unroll
                for (int e = 0; e < chf.num_elements; e++)
                    chf.x[e] = __float2half(c[i][j].x[e]);
                wmma::store_matrix_sync(dst + (size_t)(m0 + wm * 64 + i * 16) * DD
                                            + col0 + wn * 64 + j * 16,
                                        chf, DD, wmma::mem_row_major);
            }
    }
}

// ===========================================================================
// Attention (fp16 WMMA): num = expw @ EKV, den = expw @ EK per batch.
// Division in registers; only ratio staged in smem.
// Epilogue: Yt_h <- half( sigmoid(Qh + bq) * ratio ).
// Block 128(t) x 64(d), 128 threads, 4 warps (2x2), warp 64x32 dual-acc.
// 3-stage cp.async, 2 in flight, 3 CTAs/SM.
// ===========================================================================
#define A_STAGE 9728    // halves: Ws 128*40 + EK 32*72 + EKV 32*72
#define A_NST 3
#define A_SMEM (A_NST * A_STAGE * 2)   // 58368 B (epi ratio: 128*68*4 = 34816)

__global__ __launch_bounds__(128, 3)
void attnh(const __half* __restrict__ expw, const __half* __restrict__ EK,
           const __half* __restrict__ EKV, const __half* __restrict__ Qh,
           const float* __restrict__ bq, __half* __restrict__ Yt)
{
    extern __shared__ __half sh[];
    const int tid = threadIdx.x;
    const int wid = tid >> 5;
    const int wm = wid >> 1;          // 0..1 (64 t-rows)
    const int wn = wid & 1;           // 0..1 (32 d-cols)
    const int d0 = blockIdx.x * 64, t0 = blockIdx.y * 128, b = blockIdx.z;

    const __half* ekb  = EK  + (size_t)b * TT * DD;
    const __half* ekvb = EKV + (size_t)b * TT * DD;

    wmma::fragment<wmma::accumulator, 16, 16, 16, float> cN[4][2], cD[4][2];
#pragma unroll
    for (int i = 0; i < 4; i++)
#pragma unroll
        for (int j = 0; j < 2; j++) {
            wmma::fill_fragment(cN[i][j], 0.0f);
            wmma::fill_fragment(cD[i][j], 0.0f);
        }

    auto issue = [&](int chunk) {
        __half* Ws  = sh + (chunk % A_NST) * A_STAGE;
        __half* EKs = Ws + 128 * 40;
        __half* EVs = EKs + 32 * 72;
        const int s0 = chunk * 32;
#pragma unroll
        for (int i = 0; i < 4; i++) {          // Ws: 128x32 -> 512 cp16
            const int f = tid + i * 128;
            const int row = f >> 2, c8 = f & 3;
            CP16(Ws + row * 40 + c8 * 8, expw + (size_t)(t0 + row) * TT + s0 + c8 * 8);
        }
#pragma unroll
        for (int i = 0; i < 2; i++) {          // EK/EKV: 32x64 -> 256 cp16 each
            const int f = tid + i * 128;
            const int row = f >> 3, c8 = f & 7;
            CP16(EKs + row * 72 + c8 * 8, ekb  + (size_t)(s0 + row) * DD + d0 + c8 * 8);
            CP16(EVs + row * 72 + c8 * 8, ekvb + (size_t)(s0 + row) * DD + d0 + c8 * 8);
        }
        CP_COMMIT();
    };

    issue(0); issue(1);

    const int NC = TT / 32;   // 32
    for (int ch = 0; ch < NC; ch++) {
        if (ch <= NC - 2) CP_WAIT1();
        else              CP_WAIT0();
        __syncthreads();
        if (ch + 2 < NC) issue(ch + 2);

        const __half* Ws  = sh + (ch % A_NST) * A_STAGE;
        const __half* EKs = Ws + 128 * 40;
        const __half* EVs = EKs + 32 * 72;
#pragma unroll
        for (int kk = 0; kk < 2; kk++) {
            wmma::fragment<wmma::matrix_a, 16, 16, 16, __half, wmma::row_major> a[4];
            wmma::fragment<wmma::matrix_b, 16, 16, 16, __half, wmma::row_major> bK[2], bV[2];
#pragma unroll
            for (int i = 0; i < 4; i++)
                wmma::load_matrix_sync(a[i], Ws + (wm * 64 + i * 16) * 40 + kk * 16, 40);
#pragma unroll
            for (int j = 0; j < 2; j++) {
                wmma::load_matrix_sync(bK[j], EKs + (kk * 16) * 72 + wn * 32 + j * 16, 72);
                wmma::load_matrix_sync(bV[j], EVs + (kk * 16) * 72 + wn * 32 + j * 16, 72);
            }
#pragma unroll
            for (int i = 0; i < 4; i++)
#pragma unroll
                for (int j = 0; j < 2; j++) {
                    wmma::mma_sync(cN[i][j], a[i], bV[j], cN[i][j]);
                    wmma::mma_sync(cD[i][j], a[i], bK[j], cD[i][j]);
                }
        }
    }

    // Divide in registers (cN/cD element-aligned), stage only the ratio
    __syncthreads();
    float* ratio = (float*)sh;           // [128][68]
#pragma unroll
    for (int i = 0; i < 4; i++)
#pragma unroll
        for (int j = 0; j < 2; j++) {
#pragma unroll
            for (int e = 0; e < cN[i][j].num_elements; e++)
                cN[i][j].x[e] /= cD[i][j].x[e];
            wmma::store_matrix_sync(&ratio[(wm * 64 + i * 16) * 68 + wn * 32 + j * 16],
                                    cN[i][j], 68, wmma::mem_row_major);
        }
    __syncthreads();

#pragma unroll
    for (int it = 0; it < 16; it++) {
        const int f = tid + it * 128;        // 0..2047 groups of 4 over 128x64
        const int row = f >> 4, c4 = f & 15;
        const size_t qidx = ((size_t)b * TT + t0 + row) * DD + d0 + c4 * 4;
        const __half2* qp = (const __half2*)(Qh + qidx);
        float2 q01 = __half22float2(qp[0]);
        float2 q23 = __half22float2(qp[1]);
        float4 b4 = __ldg((const float4*)(bq + d0 + c4 * 4));
        const float* rp = &ratio[row * 68 + c4 * 4];
        float ox = (1.f / (1.f + expf(-(q01.x + b4.x)))) * rp[0];
        float oy = (1.f / (1.f + expf(-(q01.y + b4.y)))) * rp[1];
        float oz = (1.f / (1.f + expf(-(q23.x + b4.z)))) * rp[2];
        float ow = (1.f / (1.f + expf(-(q23.y + b4.w)))) * rp[3];
        __half2* yp = (__half2*)(Yt + qidx);
        yp[0] = __floats2half2_rn(ox, oy);
        yp[1] = __floats2half2_rn(oz, ow);
    }
}

// ===========================================================================
// Elementwise / conversion kernels
// ===========================================================================
__global__ __launch_bounds__(256)
void expw_kernel(const float* __restrict__ w, __half* __restrict__ ew)
{
    const int t = blockIdx.x;
    const float* row = w + (size_t)t * TT;
    float m = -INFINITY;
    for (int i = threadIdx.x; i < TT; i += 256) m = fmaxf(m, row[i]);
#pragma unroll
    for (int o = 16; o > 0; o >>= 1) m = fmaxf(m, __shfl_xor_sync(0xffffffffu, m, o));
    __shared__ float warpmax[8];
    __shared__ float rowmax;
    if ((threadIdx.x & 31) == 0) warpmax[threadIdx.x >> 5] = m;
    __syncthreads();
    if (threadIdx.x == 0) {
        float mm = warpmax[0];
#pragma unroll
        for (int i = 1; i < 8; i++) mm = fmaxf(mm, warpmax[i]);
        rowmax = mm;
    }
    __syncthreads();
    const float rm = rowmax;
    for (int i = threadIdx.x; i < TT; i += 256)
        ew[(size_t)t * TT + i] = __float2half(expf(row[i] - rm));
}

// Fused batch-max + exp + bias-fold over half K/V (half2 lanes)
__global__ __launch_bounds__(256)
void kmax_ekv_kernel(const __half* __restrict__ Kh, const __half* __restrict__ Vh,
                     const float* __restrict__ bv,
                     __half* __restrict__ EK, __half* __restrict__ EKV)
{
    const int idx = (blockIdx.x * 256 + threadIdx.x) * 2;   // < TT*DD
    const float bv0 = bv[idx & (DD - 1)];
    const float bv1 = bv[(idx + 1) & (DD - 1)];
    float2 kv[BB];
    float m0 = -INFINITY, m1 = -INFINITY;
#pragma unroll
    for (int b = 0; b < BB; b++) {
        kv[b] = __half22float2(*(const __half2*)(Kh + (size_t)b * TT * DD + idx));
        m0 = fmaxf(m0, kv[b].x);
        m1 = fmaxf(m1, kv[b].y);
    }
#pragma unroll
    for (int b = 0; b < BB; b++) {
        const size_t gi = (size_t)b * TT * DD + idx;
        float2 v = __half22float2(*(const __half2*)(Vh + gi));
        const float e0 = expf(kv[b].x - m0);
        const float e1 = expf(kv[b].y - m1);
        *(__half2*)(EK + gi)  = __floats2half2_rn(e0, e1);
        *(__half2*)(EKV + gi) = __floats2half2_rn(e0 * (v.x + bv0), e1 * (v.y + bv1));
    }
}

__global__ void brep_fill(const float* __restrict__ bo, float* __restrict__ brep)
{
    const int idx = blockIdx.x * 256 + threadIdx.x;
    brep[idx] = bo[idx & (DD - 1)];
}

__global__ __launch_bounds__(256)
void f2h_kernel(const float* __restrict__ src, __half* __restrict__ dst)
{
    const size_t f = (size_t)blockIdx.x * 256 + threadIdx.x;   // f4 index
    float4 v = ((const float4*)src)[f];
    __half2* d = (__half2*)(dst + f * 4);
    d[0] = __floats2half2_rn(v.x, v.y);
    d[1] = __floats2half2_rn(v.z, v.w);
}

__global__ __launch_bounds__(256)
void wconv_kernel(const float* __restrict__ Wk, const float* __restrict__ Wv,
                  const float* __restrict__ Wq, const float* __restrict__ Wo,
                  __half* __restrict__ W3h, __half* __restrict__ Woh)
{
    const int f = blockIdx.x * 256 + threadIdx.x;    // f4 index < 4*65536
    const int per = DD * DD / 4;
    const float* src; __half* dst; int off;
    if (f < per)           { src = Wk; dst = W3h;            off = f; }
    else if (f < 2 * per)  { src = Wv; dst = W3h + DD * DD;  off = f - per; }
    else if (f < 3 * per)  { src = Wq; dst = W3h + 2*DD*DD;  off = f - 2 * per; }
    else                   { src = Wo; dst = Woh;            off = f - 3 * per; }
    float4 v = ((const float4*)src)[off];
    __half2* d = (__half2*)(dst + (size_t)off * 4);
    d[0] = __floats2half2_rn(v.x, v.y);
    d[1] = __floats2half2_rn(v.z, v.w);
}

// ===========================================================================
extern "C" void kernel_launch(void* const* d_in, const int* in_sizes, int n_in,
                              void* d_out, int out_size)
{
    const float* x    = (const float*)d_in[0];
    const float* Wk_w = (const float*)d_in[1];
    // Wk_b unused: K bias cancels inside exp(K - max_b K)
    const float* Wv_w = (const float*)d_in[3];
    const float* Wv_b = (const float*)d_in[4];
    const float* Wq_w = (const float*)d_in[5];
    const float* Wq_b = (const float*)d_in[6];
    const float* w    = (const float*)d_in[7];
    const float* Wo_w = (const float*)d_in[8];
    const float* Wo_b = (const float*)d_in[9];
    float* out = (float*)d_out;

    float *pbrep;
    __half *pKh, *pVh, *pQh, *pxh, *pW3h, *pWoh, *pexpwh, *pEKh, *pEKVh, *pYth;
    cudaGetSymbolAddress((void**)&pbrep, g_brep);
    cudaGetSymbolAddress((void**)&pKh, g_Kh);
    cudaGetSymbolAddress((void**)&pVh, g_Vh);
    cudaGetSymbolAddress((void**)&pQh, g_Qh);
    cudaGetSymbolAddress((void**)&pxh, g_xh);
    cudaGetSymbolAddress((void**)&pW3h, g_W3h);
    cudaGetSymbolAddress((void**)&pWoh, g_Woh);
    cudaGetSymbolAddress((void**)&pexpwh, g_expwh);
    cudaGetSymbolAddress((void**)&pEKh, g_EKh);
    cudaGetSymbolAddress((void**)&pEKVh, g_EKVh);
    cudaGetSymbolAddress((void**)&pYth, g_Yth);

    cudaFuncSetAttribute(linh,  cudaFuncAttributeMaxDynamicSharedMemorySize, L_SMEM);
    cudaFuncSetAttribute(attnh, cudaFuncAttributeMaxDynamicSharedMemorySize, A_SMEM);

    // Prep (ordered so launch #4 = fused KVQ GEMM, which ncu captures)
    f2h_kernel<<<(MM * DD / 4) / 256, 256>>>(x, pxh);
    wconv_kernel<<<(4 * DD * DD / 4) / 256, 256>>>(Wk_w, Wv_w, Wq_w, Wo_w, pW3h, pWoh);
    expw_kernel<<<TT, 256>>>(w, pexpwh);

    // #4: fused K/V/Q linear (half out): N = 1536 -> grid (12, 256)
    linh<<<dim3(12, MM / 128), 128, L_SMEM>>>(pxh, pW3h, pbrep, pKh, pVh, pQh, nullptr);

    brep_fill<<<(16 * DD) / 256, 256>>>(Wo_b, pbrep);
    kmax_ekv_kernel<<<(TT * DD / 2) / 256, 256>>>(pKh, pVh, Wv_b, pEKh, pEKVh);

    attnh<<<dim3(DD / 64, TT / 128, BB), 128, A_SMEM>>>(pexpwh, pEKh, pEKVh, pQh, Wq_b, pYth);

    // Final linear with bias (fp32 out): N = 512 -> grid (4, 256)
    linh<<<dim3(4, MM / 128), 128, L_SMEM>>>(pYth, pWoh, pbrep, nullptr, nullptr, nullptr, out);
}